// round 8
// baseline (speedup 1.0000x reference)
#include <cuda_runtime.h>
#include <cuda_bf16.h>
#include <math.h>
#include <stdint.h>

// ---------------------------------------------------------------------------
// Problem constants (Mamba2 block)
// ---------------------------------------------------------------------------
#define BATCH     2
#define SEQLEN    4096
#define DMODEL    1024
#define DSTATE    128
#define DCONV     4
#define HEADDIM   64
#define DINNER    2048
#define NHEADS    32
#define CONVDIM   2304              // DINNER + 2*DSTATE
#define DINPROJ   4384              // 2*DINNER + 2*DSTATE + NHEADS
#define ROWS      (BATCH*SEQLEN)    // 8192
#define DTCOL     (2*DINNER + 2*DSTATE)   // 4352

#define T_CH      64                // chunk length
#define NCHUNK    (SEQLEN / T_CH)   // 64 chunks per (b,h)
#define NCTA_CH   (BATCH * NHEADS * NCHUNK)   // 4096

// Scratch (allocation-free rule: __device__ globals)
__device__ float g_zxbcdt[(size_t)ROWS * DINPROJ];
__device__ float g_conv  [(size_t)ROWS * CONVDIM];
__device__ float g_y     [(size_t)ROWS * DINNER];
__device__ float g_xtf   [(size_t)ROWS * DMODEL];
__device__ float g_w1tf  [(size_t)DMODEL * DINPROJ];
__device__ float g_w2tf  [(size_t)DINNER * DMODEL];
__device__ float g_dt    [(size_t)ROWS * NHEADS];
__device__ float g_sinc  [(size_t)NCTA_CH * HEADDIM * DSTATE];
__device__ float g_state0[(size_t)NCTA_CH * HEADDIM * DSTATE];
__device__ float g_et    [(size_t)NCTA_CH * T_CH];
__device__ float g_cdec  [(size_t)NCTA_CH];

__device__ __forceinline__ uint32_t f2tf32(float f) {
    uint32_t r;
    asm("cvt.rna.tf32.f32 %0, %1;" : "=r"(r) : "f"(f));
    return r;
}
__device__ __forceinline__ float tfr(float f) {
    return __uint_as_float(f2tf32(f));
}
__device__ __forceinline__ uint32_t smem_addr(const void* p) {
    return (uint32_t)__cvta_generic_to_shared(p);
}
__device__ __forceinline__ void cp16(uint32_t dst, const void* src, int sz) {
    asm volatile("cp.async.cg.shared.global [%0], [%1], 16, %2;"
                 :: "r"(dst), "l"(src), "r"(sz) : "memory");
}
#define CP_COMMIT() asm volatile("cp.async.commit_group;" ::: "memory")
#define CP_WAIT(n)  asm volatile("cp.async.wait_group %0;" :: "n"(n) : "memory")

#define MMA_TF32(acc, a0, a1, a2, a3, b0, b1)                               \
    asm volatile(                                                           \
        "mma.sync.aligned.m16n8k8.row.col.f32.tf32.tf32.f32 "               \
        "{%0,%1,%2,%3}, {%4,%5,%6,%7}, {%8,%9}, {%0,%1,%2,%3};"             \
        : "+f"((acc)[0]), "+f"((acc)[1]), "+f"((acc)[2]), "+f"((acc)[3])    \
        : "r"(a0), "r"(a1), "r"(a2), "r"(a3), "r"(b0), "r"(b1))

// ---------------------------------------------------------------------------
// Elementwise tf32 rounding pre-pass
// ---------------------------------------------------------------------------
__global__ void cvt_tf32_kernel(const float* __restrict__ in,
                                float* __restrict__ out, long n4)
{
    long i = (long)blockIdx.x * blockDim.x + threadIdx.x;
    if (i >= n4) return;
    float4 v = ((const float4*)in)[i];
    float4 o = make_float4(tfr(v.x), tfr(v.y), tfr(v.z), tfr(v.w));
    ((float4*)out)[i] = o;
}

// ---------------------------------------------------------------------------
// TF32 mma.sync GEMM, 3-stage cp.async pipeline.
// CTA tile 128x256, BK=32, 256 threads (8 warps, 2x4), warp tile 64x64.
// LDS-BW optimized: bytes/flop = 2(M+N)/(MN) = 0.0625 (was 0.094 at 64x32).
// As[128][36]: A-frag bank = 4g+t4 (bijective). Bs[32][264]: 264 % 32 == 8,
// bf bank = 8*t4+g (bijective). 1 CTA/SM (128 acc regs/thread).
// ---------------------------------------------------------------------------
#define GSTAGES 3
#define ASTR 36
#define BSTR 264
#define BN   256
#define STAGE_WORDS (128*ASTR + 32*BSTR)            // 13056 words
#define GEMM_SMEM   (GSTAGES * STAGE_WORDS * 4)     // 156672 B

__global__ __launch_bounds__(256, 1)
void tf32_gemm_kernel(const float* __restrict__ A, const float* __restrict__ B,
                      float* __restrict__ C, int M, int N, int K)
{
    extern __shared__ uint32_t smem[];

    const int tid   = threadIdx.x;
    const int warp  = tid >> 5;
    const int lane  = tid & 31;
    const int g     = lane >> 2;
    const int t4    = lane & 3;
    const int warpM = warp >> 2;       // 0..1 (64-row tiles)
    const int warpN = warp & 3;        // 0..3 (64-col tiles)
    const int rowC  = blockIdx.y * 128;
    const int colC  = blockIdx.x * BN;
    const int NC    = K / 32;

    auto stage_cp = [&](int chunk, int slot) {
        uint32_t* As = smem + slot * STAGE_WORDS;
        uint32_t* Bs = As + 128 * ASTR;
        const int k0 = chunk * 32;
        // A: 128 x 32 = 1024 float4, 4 per thread
        #pragma unroll
        for (int p = 0; p < 4; p++) {
            int i = p * 256 + tid;
            int m = i >> 3, kq = i & 7;
            cp16(smem_addr(As + m * ASTR + kq * 4),
                 A + (size_t)(rowC + m) * K + k0 + kq * 4, 16);
        }
        // B: 32 x 256 = 2048 float4, 8 per thread
        #pragma unroll
        for (int p = 0; p < 8; p++) {
            int i = p * 256 + tid;
            int kl = i >> 6, nq = i & 63;
            int gcol = colC + nq * 4;
            int ok = (gcol < N);
            cp16(smem_addr(Bs + kl * BSTR + nq * 4),
                 B + (size_t)(k0 + kl) * N + (ok ? gcol : 0), ok ? 16 : 0);
        }
    };

    float acc[4][8][4];
    #pragma unroll
    for (int mi = 0; mi < 4; mi++)
        #pragma unroll
        for (int ni = 0; ni < 8; ni++)
            #pragma unroll
            for (int r = 0; r < 4; r++) acc[mi][ni][r] = 0.f;

    stage_cp(0, 0); CP_COMMIT();
    stage_cp(1, 1); CP_COMMIT();

    for (int i = 0; i < NC; i++) {
        if (i < NC - 1) CP_WAIT(1); else CP_WAIT(0);
        __syncthreads();
        if (i + 2 < NC) { stage_cp(i + 2, (i + 2) % GSTAGES); CP_COMMIT(); }

        const uint32_t* As = smem + (i % GSTAGES) * STAGE_WORDS;
        const uint32_t* Bs = As + 128 * ASTR;

        #pragma unroll
        for (int ks = 0; ks < 4; ks++) {
            const int kk = ks * 8;
            uint32_t af[4][4];
            #pragma unroll
            for (int mi = 0; mi < 4; mi++) {
                int m = warpM * 64 + mi * 16;
                af[mi][0] = As[(m + g)     * ASTR + kk + t4];
                af[mi][1] = As[(m + g + 8) * ASTR + kk + t4];
                af[mi][2] = As[(m + g)     * ASTR + kk + t4 + 4];
                af[mi][3] = As[(m + g + 8) * ASTR + kk + t4 + 4];
            }
            uint32_t bf[8][2];
            #pragma unroll
            for (int ni = 0; ni < 8; ni++) {
                int n = warpN * 64 + ni * 8 + g;
                bf[ni][0] = Bs[(kk + t4)     * BSTR + n];
                bf[ni][1] = Bs[(kk + t4 + 4) * BSTR + n];
            }
            #pragma unroll
            for (int mi = 0; mi < 4; mi++)
                #pragma unroll
                for (int ni = 0; ni < 8; ni++)
                    MMA_TF32(acc[mi][ni], af[mi][0], af[mi][1], af[mi][2],
                             af[mi][3], bf[ni][0], bf[ni][1]);
        }
    }

    #pragma unroll
    for (int mi = 0; mi < 4; mi++) {
        int r0 = rowC + warpM * 64 + mi * 16 + g;
        #pragma unroll
        for (int ni = 0; ni < 8; ni++) {
            int cc = colC + warpN * 64 + ni * 8 + t4 * 2;
            if (cc < N) {
                *(float2*)(C + (size_t)r0 * N + cc)       =
                    make_float2(acc[mi][ni][0], acc[mi][ni][1]);
                *(float2*)(C + (size_t)(r0 + 8) * N + cc) =
                    make_float2(acc[mi][ni][2], acc[mi][ni][3]);
            }
        }
    }
}

// ---------------------------------------------------------------------------
// Causal depthwise conv1d (K=4) + SiLU
// ---------------------------------------------------------------------------
__global__ void conv_silu_kernel(const float* __restrict__ zxbcdt,
                                 const float* __restrict__ conv_w,
                                 const float* __restrict__ conv_b,
                                 float* __restrict__ out)
{
    long idx = (long)blockIdx.x * blockDim.x + threadIdx.x;
    const long total = (long)ROWS * CONVDIM;
    if (idx >= total) return;
    int  c = (int)(idx % CONVDIM);
    long r = idx / CONVDIM;
    int  l = (int)(r & (SEQLEN - 1));

    const float* xcol = zxbcdt + r * DINPROJ + DINNER + c;
    float acc = conv_b[c];
    #pragma unroll
    for (int j = 0; j < DCONV; j++) {
        if (l - j >= 0)
            acc = fmaf(conv_w[j * CONVDIM + c], xcol[-(long)j * DINPROJ], acc);
    }
    out[idx] = acc / (1.f + expf(-acc));
}

// ---------------------------------------------------------------------------
// dt precompute: dt = softplus(dt_raw + bias)
// ---------------------------------------------------------------------------
__global__ void dt_kernel(const float* __restrict__ zxbcdt,
                          const float* __restrict__ dt_bias,
                          float* __restrict__ dt_out)
{
    long idx = (long)blockIdx.x * blockDim.x + threadIdx.x;
    if (idx >= (long)ROWS * NHEADS) return;
    int  h = (int)(idx & (NHEADS - 1));
    long r = idx >> 5;
    float v  = zxbcdt[r * DINPROJ + DTCOL + h] + dt_bias[h];
    dt_out[idx] = (v > 20.f) ? v : log1pf(expf(v));
}

// ---------------------------------------------------------------------------
// Chunked scan, intra-chunk kernel (unchanged from R7-passing).
// ---------------------------------------------------------------------------
#define CH_SMEM ((64*132 + 64*132 + 64*68 + 64*68 + 4*64) * 4)

__global__ __launch_bounds__(256, 2)
void chunk_kernel(const float* __restrict__ convout,
                  const float* __restrict__ dtbuf,
                  const float* __restrict__ A_log,
                  const float* __restrict__ Dparam,
                  float* __restrict__ y,
                  float* __restrict__ sinc,
                  float* __restrict__ etbuf,
                  float* __restrict__ cdec)
{
    extern __shared__ float sm[];
    float* Bs  = sm;                  // [64][132]  B[t][n]
    float* Cs  = Bs + 64 * 132;       // [64][132]  C[t][n]; reused as Ms
    float* Xs  = Cs + 64 * 132;       // [64][68]   x[t][p]
    float* Xw  = Xs + 64 * 68;        // [64][68]   weighted x^T [p][t]
    float* sS  = Xw + 64 * 68;
    float* sdt = sS + 64;
    float* swS = sdt + 64;
    float* Ms  = Cs;

    const int ci    = blockIdx.x;
    const int chunk = ci & (NCHUNK - 1);
    const int h     = (ci >> 6) & (NHEADS - 1);
    const int b     = ci >> 11;
    const long r0   = (long)b * SEQLEN + chunk * T_CH;
    const int tid   = threadIdx.x;
    const int warp  = tid >> 5;
    const int lane  = tid & 31;
    const int g     = lane >> 2;
    const int t4    = lane & 3;
    const int wM    = warp >> 2;
    const int wN    = warp & 3;

    const float A  = -expf(A_log[h]);
    const float Dh = Dparam[h];

    #pragma unroll
    for (int j = 0; j < 8; j++) {
        int idx = j * 256 + tid;
        int t = idx >> 5, q = idx & 31;
        const float* row = convout + (r0 + t) * CONVDIM;
        float4 vb = *(const float4*)(row + DINNER + q * 4);
        float* db = &Bs[t * 132 + q * 4];
        db[0] = tfr(vb.x); db[1] = tfr(vb.y); db[2] = tfr(vb.z); db[3] = tfr(vb.w);
        float4 vc = *(const float4*)(row + DINNER + DSTATE + q * 4);
        float* dc = &Cs[t * 132 + q * 4];
        dc[0] = tfr(vc.x); dc[1] = tfr(vc.y); dc[2] = tfr(vc.z); dc[3] = tfr(vc.w);
    }
    #pragma unroll
    for (int j = 0; j < 4; j++) {
        int idx = j * 256 + tid;
        int t = idx >> 4, q = idx & 15;
        float4 v = *(const float4*)(convout + (r0 + t) * CONVDIM + h * HEADDIM + q * 4);
        float* d = &Xs[t * 68 + q * 4];
        d[0] = tfr(v.x); d[1] = tfr(v.y); d[2] = tfr(v.z); d[3] = tfr(v.w);
    }
    if (tid < 64) {
        float d = dtbuf[(r0 + tid) * NHEADS + h];
        sdt[tid] = d;
        sS[tid]  = d;
    }
    __syncthreads();

    #pragma unroll
    for (int off = 1; off < 64; off <<= 1) {
        float v = 0.f;
        if (tid < 64 && tid >= off) v = sS[tid - off];
        __syncthreads();
        if (tid < 64) sS[tid] += v;
        __syncthreads();
    }
    if (tid < 64) {
        float St = sS[tid], ST = sS[63];
        swS[tid] = sdt[tid] * __expf(A * (ST - St));
        etbuf[(size_t)ci * T_CH + tid] = __expf(A * St);
    }
    if (tid == 0) cdec[ci] = __expf(A * sS[63]);
    __syncthreads();

    float acc[2][2][4];
    #pragma unroll
    for (int mi = 0; mi < 2; mi++)
        #pragma unroll
        for (int ni = 0; ni < 2; ni++)
            #pragma unroll
            for (int r = 0; r < 4; r++) acc[mi][ni][r] = 0.f;

    #pragma unroll
    for (int ks = 0; ks < 16; ks++) {
        const int kk = ks * 8;
        uint32_t af[2][4], bf[2][2];
        #pragma unroll
        for (int mi = 0; mi < 2; mi++) {
            int m = wM * 32 + mi * 16;
            af[mi][0] = __float_as_uint(Cs[(m + g)     * 132 + kk + t4]);
            af[mi][1] = __float_as_uint(Cs[(m + g + 8) * 132 + kk + t4]);
            af[mi][2] = __float_as_uint(Cs[(m + g)     * 132 + kk + t4 + 4]);
            af[mi][3] = __float_as_uint(Cs[(m + g + 8) * 132 + kk + t4 + 4]);
        }
        #pragma unroll
        for (int ni = 0; ni < 2; ni++) {
            int s = wN * 16 + ni * 8 + g;
            bf[ni][0] = __float_as_uint(Bs[s * 132 + kk + t4]);
            bf[ni][1] = __float_as_uint(Bs[s * 132 + kk + t4 + 4]);
        }
        #pragma unroll
        for (int mi = 0; mi < 2; mi++)
            #pragma unroll
            for (int ni = 0; ni < 2; ni++)
                MMA_TF32(acc[mi][ni], af[mi][0], af[mi][1], af[mi][2],
                         af[mi][3], bf[ni][0], bf[ni][1]);
    }
    __syncthreads();

    #pragma unroll
    for (int mi = 0; mi < 2; mi++) {
        #pragma unroll
        for (int ni = 0; ni < 2; ni++) {
            int tb = wM * 32 + mi * 16;
            int sb = wN * 16 + ni * 8 + 2 * t4;
            #pragma unroll
            for (int r = 0; r < 4; r++) {
                int tt = tb + g + ((r >= 2) ? 8 : 0);
                int ss = sb + (r & 1);
                float w = 0.f;
                if (ss <= tt) w = sdt[ss] * __expf(A * (sS[tt] - sS[ss]));
                Ms[tt * 68 + ss] = tfr(acc[mi][ni][r] * w);
            }
        }
    }
    #pragma unroll
    for (int j = 0; j < 16; j++) {
        int idx = j * 256 + tid;
        int p = idx >> 6, t = idx & 63;
        Xw[p * 68 + t] = tfr(swS[t] * Xs[t * 68 + p]);
    }
    __syncthreads();

    float acc2[2][2][4];
    #pragma unroll
    for (int mi = 0; mi < 2; mi++)
        #pragma unroll
        for (int ni = 0; ni < 2; ni++)
            #pragma unroll
            for (int r = 0; r < 4; r++) acc2[mi][ni][r] = 0.f;

    #pragma unroll
    for (int ks = 0; ks < 8; ks++) {
        const int kk = ks * 8;
        uint32_t af[2][4], bf[2][2];
        #pragma unroll
        for (int mi = 0; mi < 2; mi++) {
            int m = wM * 32 + mi * 16;
            af[mi][0] = __float_as_uint(Ms[(m + g)     * 68 + kk + t4]);
            af[mi][1] = __float_as_uint(Ms[(m + g + 8) * 68 + kk + t4]);
            af[mi][2] = __float_as_uint(Ms[(m + g)     * 68 + kk + t4 + 4]);
            af[mi][3] = __float_as_uint(Ms[(m + g + 8) * 68 + kk + t4 + 4]);
        }
        #pragma unroll
        for (int ni = 0; ni < 2; ni++) {
            int p = wN * 16 + ni * 8 + g;
            bf[ni][0] = __float_as_uint(Xs[(kk + t4)     * 68 + p]);
            bf[ni][1] = __float_as_uint(Xs[(kk + t4 + 4) * 68 + p]);
        }
        #pragma unroll
        for (int mi = 0; mi < 2; mi++)
            #pragma unroll
            for (int ni = 0; ni < 2; ni++)
                MMA_TF32(acc2[mi][ni], af[mi][0], af[mi][1], af[mi][2],
                         af[mi][3], bf[ni][0], bf[ni][1]);
    }
    #pragma unroll
    for (int mi = 0; mi < 2; mi++) {
        #pragma unroll
        for (int ni = 0; ni < 2; ni++) {
            int tb = wM * 32 + mi * 16;
            int pb = wN * 16 + ni * 8 + 2 * t4;
            int t0 = tb + g, t1 = tb + g + 8;
            float2 o0 = make_float2(
                acc2[mi][ni][0] + Dh * Xs[t0 * 68 + pb],
                acc2[mi][ni][1] + Dh * Xs[t0 * 68 + pb + 1]);
            float2 o1 = make_float2(
                acc2[mi][ni][2] + Dh * Xs[t1 * 68 + pb],
                acc2[mi][ni][3] + Dh * Xs[t1 * 68 + pb + 1]);
            *(float2*)(y + (r0 + t0) * DINNER + h * HEADDIM + pb) = o0;
            *(float2*)(y + (r0 + t1) * DINNER + h * HEADDIM + pb) = o1;
        }
    }

    float acc3[2][4][4];
    #pragma unroll
    for (int mi = 0; mi < 2; mi++)
        #pragma unroll
        for (int ni = 0; ni < 4; ni++)
            #pragma unroll
            for (int r = 0; r < 4; r++) acc3[mi][ni][r] = 0.f;

    #pragma unroll
    for (int ks = 0; ks < 8; ks++) {
        const int kk = ks * 8;
        uint32_t af[2][4], bf[4][2];
        #pragma unroll
        for (int mi = 0; mi < 2; mi++) {
            int p = wM * 32 + mi * 16;
            af[mi][0] = __float_as_uint(Xw[(p + g)     * 68 + kk + t4]);
            af[mi][1] = __float_as_uint(Xw[(p + g + 8) * 68 + kk + t4]);
            af[mi][2] = __float_as_uint(Xw[(p + g)     * 68 + kk + t4 + 4]);
            af[mi][3] = __float_as_uint(Xw[(p + g + 8) * 68 + kk + t4 + 4]);
        }
        #pragma unroll
        for (int ni = 0; ni < 4; ni++) {
            int n = wN * 32 + ni * 8 + g;
            bf[ni][0] = __float_as_uint(Bs[(kk + t4)     * 132 + n]);
            bf[ni][1] = __float_as_uint(Bs[(kk + t4 + 4) * 132 + n]);
        }
        #pragma unroll
        for (int mi = 0; mi < 2; mi++)
            #pragma unroll
            for (int ni = 0; ni < 4; ni++)
                MMA_TF32(acc3[mi][ni], af[mi][0], af[mi][1], af[mi][2],
                         af[mi][3], bf[ni][0], bf[ni][1]);
    }
    #pragma unroll
    for (int mi = 0; mi < 2; mi++) {
        #pragma unroll
        for (int ni = 0; ni < 4; ni++) {
            int pb = wM * 32 + mi * 16;
            int nb = wN * 32 + ni * 8 + 2 * t4;
            size_t base = (size_t)ci * (HEADDIM * DSTATE);
            *(float2*)(sinc + base + (pb + g)     * DSTATE + nb) =
                make_float2(acc3[mi][ni][0], acc3[mi][ni][1]);
            *(float2*)(sinc + base + (pb + g + 8) * DSTATE + nb) =
                make_float2(acc3[mi][ni][2], acc3[mi][ni][3]);
        }
    }
}

// ---------------------------------------------------------------------------
// Inter-chunk sequential recurrence
// ---------------------------------------------------------------------------
__global__ __launch_bounds__(256)
void seq_kernel(const float* __restrict__ sinc,
                const float* __restrict__ cdec,
                float* __restrict__ state0)
{
    int bh = blockIdx.x;
    int b = bh >> 5, h = bh & 31;
    int tid = threadIdx.x;

    float st[32];
    #pragma unroll
    for (int j = 0; j < 32; j++) st[j] = 0.f;

    for (int k = 0; k < NCHUNK; k++) {
        int ci = b * (NHEADS * NCHUNK) + h * NCHUNK + k;
        float cd = cdec[ci];
        size_t base = (size_t)ci * (HEADDIM * DSTATE);
        #pragma unroll
        for (int j = 0; j < 32; j++) {
            size_t e = base + (size_t)j * 256 + tid;
            state0[e] = st[j];
            st[j] = fmaf(st[j], cd, sinc[e]);
        }
    }
}

// ---------------------------------------------------------------------------
// Apply inter-chunk state: y[t][p] += e^{A S_t} * sum_n C[t][n] state0[p][n]
// ---------------------------------------------------------------------------
#define AP_SMEM ((64*132 + 128*68 + 64) * 4)

__global__ __launch_bounds__(256)
void apply_kernel(const float* __restrict__ convout,
                  const float* __restrict__ state0,
                  const float* __restrict__ etbuf,
                  float* __restrict__ y)
{
    extern __shared__ float sm[];
    float* Cs  = sm;
    float* S0s = Cs + 64 * 132;
    float* set = S0s + 128 * 68;

    const int ci    = blockIdx.x;
    const int chunk = ci & (NCHUNK - 1);
    const int h     = (ci >> 6) & (NHEADS - 1);
    const int b     = ci >> 11;
    const long r0   = (long)b * SEQLEN + chunk * T_CH;
    const int tid   = threadIdx.x;
    const int warp  = tid >> 5;
    const int lane  = tid & 31;
    const int g     = lane >> 2;
    const int t4    = lane & 3;
    const int wM    = warp >> 2;
    const int wN    = warp & 3;

    #pragma unroll
    for (int j = 0; j < 8; j++) {
        int idx = j * 256 + tid;
        int t = idx >> 5, q = idx & 31;
        float4 v = *(const float4*)(convout + (r0 + t) * CONVDIM + DINNER + DSTATE + q * 4);
        float* d = &Cs[t * 132 + q * 4];
        d[0] = tfr(v.x); d[1] = tfr(v.y); d[2] = tfr(v.z); d[3] = tfr(v.w);
    }
    {
        size_t base = (size_t)ci * (HEADDIM * DSTATE);
        #pragma unroll
        for (int j = 0; j < 32; j++) {
            int idx = j * 256 + tid;
            int p = idx >> 7, n = idx & 127;
            S0s[n * 68 + p] = tfr(state0[base + idx]);
        }
    }
    if (tid < 64) set[tid] = etbuf[(size_t)ci * T_CH + tid];
    __syncthreads();

    float acc[2][2][4];
    #pragma unroll
    for (int mi = 0; mi < 2; mi++)
        #pragma unroll
        for (int ni = 0; ni < 2; ni++)
            #pragma unroll
            for (int r = 0; r < 4; r++) acc[mi][ni][r] = 0.f;

    #pragma unroll
    for (int ks = 0; ks < 16; ks++) {
        const int kk = ks * 8;
        uint32_t af[2][4], bf[2][2];
        #pragma unroll
        for (int mi = 0; mi < 2; mi++) {
            int m = wM * 32 + mi * 16;
            af[mi][0] = __float_as_uint(Cs[(m + g)     * 132 + kk + t4]);
            af[mi][1] = __float_as_uint(Cs[(m + g + 8) * 132 + kk + t4]);
            af[mi][2] = __float_as_uint(Cs[(m + g)     * 132 + kk + t4 + 4]);
            af[mi][3] = __float_as_uint(Cs[(m + g + 8) * 132 + kk + t4 + 4]);
        }
        #pragma unroll
        for (int ni = 0; ni < 2; ni++) {
            int p = wN * 16 + ni * 8 + g;
            bf[ni][0] = __float_as_uint(S0s[(kk + t4)     * 68 + p]);
            bf[ni][1] = __float_as_uint(S0s[(kk + t4 + 4) * 68 + p]);
        }
        #pragma unroll
        for (int mi = 0; mi < 2; mi++)
            #pragma unroll
            for (int ni = 0; ni < 2; ni++)
                MMA_TF32(acc[mi][ni], af[mi][0], af[mi][1], af[mi][2],
                         af[mi][3], bf[ni][0], bf[ni][1]);
    }

    #pragma unroll
    for (int mi = 0; mi < 2; mi++) {
        #pragma unroll
        for (int ni = 0; ni < 2; ni++) {
            int tb = wM * 32 + mi * 16;
            int pb = wN * 16 + ni * 8 + 2 * t4;
            int t0 = tb + g, t1 = tb + g + 8;
            float e0 = set[t0], e1 = set[t1];
            float2* a0 = (float2*)(y + (r0 + t0) * DINNER + h * HEADDIM + pb);
            float2* a1 = (float2*)(y + (r0 + t1) * DINNER + h * HEADDIM + pb);
            float2 v0 = *a0, v1 = *a1;
            v0.x += e0 * acc[mi][ni][0]; v0.y += e0 * acc[mi][ni][1];
            v1.x += e1 * acc[mi][ni][2]; v1.y += e1 * acc[mi][ni][3];
            *a0 = v0; *a1 = v1;
        }
    }
}

// ---------------------------------------------------------------------------
// Gated RMSNorm in place on y; output tf32-rounded.
// ---------------------------------------------------------------------------
__global__ __launch_bounds__(256)
void gated_rmsnorm_kernel(float* __restrict__ y,
                          const float* __restrict__ zxbcdt,
                          const float* __restrict__ norm_w)
{
    long r = blockIdx.x;
    int tid = threadIdx.x;
    float* yr = y + r * DINNER;
    const float* zr = zxbcdt + r * DINPROJ;

    float vals[8];
    float ss = 0.f;
    #pragma unroll
    for (int i = 0; i < 8; i++) {
        int c = tid + i * 256;
        float z  = zr[c];
        float gv = yr[c] * (z / (1.f + expf(-z)));
        vals[i] = gv;
        ss = fmaf(gv, gv, ss);
    }

    __shared__ float sred[256];
    sred[tid] = ss;
    __syncthreads();
    #pragma unroll
    for (int off = 128; off > 0; off >>= 1) {
        if (tid < off) sred[tid] += sred[tid + off];
        __syncthreads();
    }
    float scale = rsqrtf(sred[0] / (float)DINNER + 1e-5f);

    #pragma unroll
    for (int i = 0; i < 8; i++) {
        int c = tid + i * 256;
        yr[c] = tfr(vals[i] * scale * norm_w[c]);
    }
}

// ---------------------------------------------------------------------------
// Launch. Inputs: x, in_proj_w, conv_w, conv_b, norm_w, out_proj_w,
//                 dt_bias, A_log, D
// ---------------------------------------------------------------------------
extern "C" void kernel_launch(void* const* d_in, const int* in_sizes, int n_in,
                              void* d_out, int out_size)
{
    const float* x          = (const float*)d_in[0];
    const float* in_proj_w  = (const float*)d_in[1];
    const float* conv_w     = (const float*)d_in[2];
    const float* conv_b     = (const float*)d_in[3];
    const float* norm_w     = (const float*)d_in[4];
    const float* out_proj_w = (const float*)d_in[5];
    const float* dt_bias    = (const float*)d_in[6];
    const float* A_log      = (const float*)d_in[7];
    const float* Dparam     = (const float*)d_in[8];
    float* out = (float*)d_out;

    float *zxbcdt, *convbuf, *ybuf, *xtf, *w1tf, *w2tf, *dtb;
    float *sincb, *state0b, *etb, *cdecb;
    cudaGetSymbolAddress((void**)&zxbcdt,  g_zxbcdt);
    cudaGetSymbolAddress((void**)&convbuf, g_conv);
    cudaGetSymbolAddress((void**)&ybuf,    g_y);
    cudaGetSymbolAddress((void**)&xtf,     g_xtf);
    cudaGetSymbolAddress((void**)&w1tf,    g_w1tf);
    cudaGetSymbolAddress((void**)&w2tf,    g_w2tf);
    cudaGetSymbolAddress((void**)&dtb,     g_dt);
    cudaGetSymbolAddress((void**)&sincb,   g_sinc);
    cudaGetSymbolAddress((void**)&state0b, g_state0);
    cudaGetSymbolAddress((void**)&etb,     g_et);
    cudaGetSymbolAddress((void**)&cdecb,   g_cdec);

    cudaFuncSetAttribute(tf32_gemm_kernel,
                         cudaFuncAttributeMaxDynamicSharedMemorySize, GEMM_SMEM);
    cudaFuncSetAttribute(chunk_kernel,
                         cudaFuncAttributeMaxDynamicSharedMemorySize, CH_SMEM);
    cudaFuncSetAttribute(apply_kernel,
                         cudaFuncAttributeMaxDynamicSharedMemorySize, AP_SMEM);

    // 0) tf32 rounding pre-passes
    {
        long n4;
        n4 = (long)ROWS * DMODEL / 4;
        cvt_tf32_kernel<<<(unsigned)((n4 + 255) / 256), 256>>>(x, xtf, n4);
        n4 = (long)DMODEL * DINPROJ / 4;
        cvt_tf32_kernel<<<(unsigned)((n4 + 255) / 256), 256>>>(in_proj_w, w1tf, n4);
        n4 = (long)DINNER * DMODEL / 4;
        cvt_tf32_kernel<<<(unsigned)((n4 + 255) / 256), 256>>>(out_proj_w, w2tf, n4);
    }

    // 1) in_proj: [8192,1024] x [1024,4384], BN=256
    {
        dim3 grid((DINPROJ + BN - 1) / BN, ROWS / 128);   // 18 x 64
        tf32_gemm_kernel<<<grid, 256, GEMM_SMEM>>>(xtf, w1tf, zxbcdt,
                                                   ROWS, DINPROJ, DMODEL);
    }

    // 2) conv + silu
    {
        long total = (long)ROWS * CONVDIM;
        conv_silu_kernel<<<(unsigned)((total + 255) / 256), 256>>>(
            zxbcdt, conv_w, conv_b, convbuf);
    }

    // 3) dt precompute
    {
        long total = (long)ROWS * NHEADS;
        dt_kernel<<<(unsigned)((total + 255) / 256), 256>>>(zxbcdt, dt_bias, dtb);
    }

    // 4) chunked scan
    chunk_kernel<<<NCTA_CH, 256, CH_SMEM>>>(convbuf, dtb, A_log, Dparam,
                                            ybuf, sincb, etb, cdecb);

    // 5) inter-chunk recurrence
    seq_kernel<<<BATCH * NHEADS, 256>>>(sincb, cdecb, state0b);

    // 6) apply chunk-start states
    apply_kernel<<<NCTA_CH, 256, AP_SMEM>>>(convbuf, state0b, etb, ybuf);

    // 7) gated RMSNorm
    gated_rmsnorm_kernel<<<ROWS, 256>>>(ybuf, zxbcdt, norm_w);

    // 8) out_proj: [8192,2048] x [2048,1024], BN=256
    {
        dim3 grid(DMODEL / BN, ROWS / 128);               // 4 x 64
        tf32_gemm_kernel<<<grid, 256, GEMM_SMEM>>>(ybuf, w2tf, out,
                                                   ROWS, DMODEL, DINNER);
    }
}

// round 9
// speedup vs baseline: 1.0692x; 1.0692x over previous
#include <cuda_runtime.h>
#include <cuda_bf16.h>
#include <math.h>
#include <stdint.h>

// ---------------------------------------------------------------------------
// Problem constants (Mamba2 block)
// ---------------------------------------------------------------------------
#define BATCH     2
#define SEQLEN    4096
#define DMODEL    1024
#define DSTATE    128
#define DCONV     4
#define HEADDIM   64
#define DINNER    2048
#define NHEADS    32
#define CONVDIM   2304              // DINNER + 2*DSTATE
#define DINPROJ   4384              // 2*DINNER + 2*DSTATE + NHEADS
#define ROWS      (BATCH*SEQLEN)    // 8192
#define DTCOL     (2*DINNER + 2*DSTATE)   // 4352

#define T_CH      64
#define NCHUNK    (SEQLEN / T_CH)   // 64
#define NCTA_CH   (BATCH * NHEADS * NCHUNK)   // 4096

// Scratch (allocation-free rule: __device__ globals)
__device__ float g_zxbcdt[(size_t)ROWS * DINPROJ];
__device__ float g_conv  [(size_t)ROWS * CONVDIM];   // tf32-rounded conv+silu
__device__ float g_y     [(size_t)ROWS * DINNER];
__device__ float g_xtf   [(size_t)ROWS * DMODEL];
__device__ float g_w1tf  [(size_t)DMODEL * DINPROJ];
__device__ float g_w2tf  [(size_t)DINNER * DMODEL];
__device__ float g_dt    [(size_t)ROWS * NHEADS];
__device__ float g_sinc  [(size_t)NCTA_CH * HEADDIM * DSTATE];
__device__ float g_state0[(size_t)NCTA_CH * HEADDIM * DSTATE];  // tf32-rounded
__device__ float g_et    [(size_t)NCTA_CH * T_CH];
__device__ float g_cdec  [(size_t)NCTA_CH];

__device__ __forceinline__ uint32_t f2tf32(float f) {
    uint32_t r;
    asm("cvt.rna.tf32.f32 %0, %1;" : "=r"(r) : "f"(f));
    return r;
}
__device__ __forceinline__ float tfr(float f) {
    return __uint_as_float(f2tf32(f));
}
__device__ __forceinline__ uint32_t smem_addr(const void* p) {
    return (uint32_t)__cvta_generic_to_shared(p);
}
__device__ __forceinline__ void cp16(uint32_t dst, const void* src, int sz) {
    asm volatile("cp.async.cg.shared.global [%0], [%1], 16, %2;"
                 :: "r"(dst), "l"(src), "r"(sz) : "memory");
}
#define CP_COMMIT() asm volatile("cp.async.commit_group;" ::: "memory")
#define CP_WAIT(n)  asm volatile("cp.async.wait_group %0;" :: "n"(n) : "memory")

#define MMA_TF32(acc, a0, a1, a2, a3, b0, b1)                               \
    asm volatile(                                                           \
        "mma.sync.aligned.m16n8k8.row.col.f32.tf32.tf32.f32 "               \
        "{%0,%1,%2,%3}, {%4,%5,%6,%7}, {%8,%9}, {%0,%1,%2,%3};"             \
        : "+f"((acc)[0]), "+f"((acc)[1]), "+f"((acc)[2]), "+f"((acc)[3])    \
        : "r"(a0), "r"(a1), "r"(a2), "r"(a3), "r"(b0), "r"(b1))

// ---------------------------------------------------------------------------
// Elementwise tf32 rounding pre-pass
// ---------------------------------------------------------------------------
__global__ void cvt_tf32_kernel(const float* __restrict__ in,
                                float* __restrict__ out, long n4)
{
    long i = (long)blockIdx.x * blockDim.x + threadIdx.x;
    if (i >= n4) return;
    float4 v = ((const float4*)in)[i];
    float4 o = make_float4(tfr(v.x), tfr(v.y), tfr(v.z), tfr(v.w));
    ((float4*)out)[i] = o;
}

// ---------------------------------------------------------------------------
// TF32 mma.sync GEMM, 3-stage cp.async pipeline (R7 config: 128x128, 2 CTA/SM)
// ---------------------------------------------------------------------------
#define GSTAGES 3
#define ASTR 36
#define BSTR 136
#define STAGE_WORDS (128*ASTR + 32*BSTR)
#define GEMM_SMEM   (GSTAGES * STAGE_WORDS * 4)

__global__ __launch_bounds__(256, 2)
void tf32_gemm_kernel(const float* __restrict__ A, const float* __restrict__ B,
                      float* __restrict__ C, int M, int N, int K)
{
    extern __shared__ uint32_t smem[];

    const int tid   = threadIdx.x;
    const int warp  = tid >> 5;
    const int lane  = tid & 31;
    const int g     = lane >> 2;
    const int t4    = lane & 3;
    const int warpM = warp >> 2;
    const int warpN = warp & 3;
    const int rowC  = blockIdx.y * 128;
    const int colC  = blockIdx.x * 128;
    const int NC    = K / 32;

    auto stage_cp = [&](int chunk, int slot) {
        uint32_t* As = smem + slot * STAGE_WORDS;
        uint32_t* Bs = As + 128 * ASTR;
        const int k0 = chunk * 32;
        #pragma unroll
        for (int p = 0; p < 4; p++) {
            int i = p * 256 + tid;
            int m = i >> 3, kq = i & 7;
            cp16(smem_addr(As + m * ASTR + kq * 4),
                 A + (size_t)(rowC + m) * K + k0 + kq * 4, 16);
        }
        #pragma unroll
        for (int p = 0; p < 4; p++) {
            int i = p * 256 + tid;
            int kl = i >> 5, nq = i & 31;
            int gcol = colC + nq * 4;
            int ok = (gcol < N);
            cp16(smem_addr(Bs + kl * BSTR + nq * 4),
                 B + (size_t)(k0 + kl) * N + (ok ? gcol : 0), ok ? 16 : 0);
        }
    };

    float acc[4][4][4];
    #pragma unroll
    for (int mi = 0; mi < 4; mi++)
        #pragma unroll
        for (int ni = 0; ni < 4; ni++)
            #pragma unroll
            for (int r = 0; r < 4; r++) acc[mi][ni][r] = 0.f;

    stage_cp(0, 0); CP_COMMIT();
    stage_cp(1, 1); CP_COMMIT();

    for (int i = 0; i < NC; i++) {
        if (i < NC - 1) CP_WAIT(1); else CP_WAIT(0);
        __syncthreads();
        if (i + 2 < NC) { stage_cp(i + 2, (i + 2) % GSTAGES); CP_COMMIT(); }

        const uint32_t* As = smem + (i % GSTAGES) * STAGE_WORDS;
        const uint32_t* Bs = As + 128 * ASTR;

        #pragma unroll
        for (int ks = 0; ks < 4; ks++) {
            const int kk = ks * 8;
            uint32_t af[4][4];
            #pragma unroll
            for (int mi = 0; mi < 4; mi++) {
                int m = warpM * 64 + mi * 16;
                af[mi][0] = As[(m + g)     * ASTR + kk + t4];
                af[mi][1] = As[(m + g + 8) * ASTR + kk + t4];
                af[mi][2] = As[(m + g)     * ASTR + kk + t4 + 4];
                af[mi][3] = As[(m + g + 8) * ASTR + kk + t4 + 4];
            }
            uint32_t bf[4][2];
            #pragma unroll
            for (int ni = 0; ni < 4; ni++) {
                int n = warpN * 32 + ni * 8 + g;
                bf[ni][0] = Bs[(kk + t4)     * BSTR + n];
                bf[ni][1] = Bs[(kk + t4 + 4) * BSTR + n];
            }
            #pragma unroll
            for (int mi = 0; mi < 4; mi++)
                #pragma unroll
                for (int ni = 0; ni < 4; ni++)
                    MMA_TF32(acc[mi][ni], af[mi][0], af[mi][1], af[mi][2],
                             af[mi][3], bf[ni][0], bf[ni][1]);
        }
    }

    #pragma unroll
    for (int mi = 0; mi < 4; mi++) {
        int r0 = rowC + warpM * 64 + mi * 16 + g;
        #pragma unroll
        for (int ni = 0; ni < 4; ni++) {
            int cc = colC + warpN * 32 + ni * 8 + t4 * 2;
            if (cc < N) {
                *(float2*)(C + (size_t)r0 * N + cc)       =
                    make_float2(acc[mi][ni][0], acc[mi][ni][1]);
                *(float2*)(C + (size_t)(r0 + 8) * N + cc) =
                    make_float2(acc[mi][ni][2], acc[mi][ni][3]);
            }
        }
    }
}

// ---------------------------------------------------------------------------
// Causal depthwise conv1d (K=4) + SiLU, sliding-window, 8 timesteps/thread.
// Output tf32-rounded (consumers feed MMA fragments directly).
// y[l] = silu(conv_b + sum_j conv_w[j] * x[l-j])
// ---------------------------------------------------------------------------
__global__ __launch_bounds__(256)
void conv_silu_kernel(const float* __restrict__ zxbcdt,
                      const float* __restrict__ conv_w,
                      const float* __restrict__ conv_b,
                      float* __restrict__ out)
{
    const int  c  = blockIdx.x * 256 + threadIdx.x;     // CONVDIM = 9*256
    const long r0 = (long)blockIdx.y * 8;               // row group of 8
    const int  l0 = (int)(r0 & (SEQLEN - 1));

    const float w0 = conv_w[0 * CONVDIM + c];
    const float w1 = conv_w[1 * CONVDIM + c];
    const float w2 = conv_w[2 * CONVDIM + c];
    const float w3 = conv_w[3 * CONVDIM + c];
    const float bias = conv_b[c];

    const float* base = zxbcdt + r0 * DINPROJ + DINNER + c;
    float xm3 = 0.f, xm2 = 0.f, xm1 = 0.f;
    if (l0 > 0) {                       // groups of 8: l0>0 implies l0>=8
        xm3 = base[-3 * (long)DINPROJ];
        xm2 = base[-2 * (long)DINPROJ];
        xm1 = base[-1 * (long)DINPROJ];
    }
    float* orow = out + r0 * CONVDIM + c;
    #pragma unroll
    for (int i = 0; i < 8; i++) {
        float x0 = base[(long)i * DINPROJ];
        float acc = bias + w0 * x0 + w1 * xm1 + w2 * xm2 + w3 * xm3;
        float s = acc / (1.f + expf(-acc));
        orow[(long)i * CONVDIM] = tfr(s);
        xm3 = xm2; xm2 = xm1; xm1 = x0;
    }
}

// ---------------------------------------------------------------------------
// dt precompute: dt = softplus(dt_raw + bias)
// ---------------------------------------------------------------------------
__global__ void dt_kernel(const float* __restrict__ zxbcdt,
                          const float* __restrict__ dt_bias,
                          float* __restrict__ dt_out)
{
    long idx = (long)blockIdx.x * blockDim.x + threadIdx.x;
    if (idx >= (long)ROWS * NHEADS) return;
    int  h = (int)(idx & (NHEADS - 1));
    long r = idx >> 5;
    float v  = zxbcdt[r * DINPROJ + DTCOL + h] + dt_bias[h];
    dt_out[idx] = (v > 20.f) ? v : log1pf(expf(v));
}

// ---------------------------------------------------------------------------
// Chunked scan, intra-chunk kernel. cp.async staging (inputs pre-rounded).
// ---------------------------------------------------------------------------
#define CH_SMEM ((64*132 + 64*132 + 64*68 + 64*68 + 4*64) * 4)

__global__ __launch_bounds__(256, 2)
void chunk_kernel(const float* __restrict__ convout,
                  const float* __restrict__ dtbuf,
                  const float* __restrict__ A_log,
                  const float* __restrict__ Dparam,
                  float* __restrict__ y,
                  float* __restrict__ sinc,
                  float* __restrict__ etbuf,
                  float* __restrict__ cdec)
{
    extern __shared__ float sm[];
    float* Bs  = sm;                  // [64][132]  B[t][n]
    float* Cs  = Bs + 64 * 132;       // [64][132]  C[t][n]; reused as Ms
    float* Xs  = Cs + 64 * 132;       // [64][68]   x[t][p]
    float* Xw  = Xs + 64 * 68;        // [64][68]   weighted x^T [p][t]
    float* sS  = Xw + 64 * 68;
    float* sdt = sS + 64;
    float* swS = sdt + 64;
    float* Ms  = Cs;

    const int ci    = blockIdx.x;
    const int chunk = ci & (NCHUNK - 1);
    const int h     = (ci >> 6) & (NHEADS - 1);
    const int b     = ci >> 11;
    const long r0   = (long)b * SEQLEN + chunk * T_CH;
    const int tid   = threadIdx.x;
    const int warp  = tid >> 5;
    const int lane  = tid & 31;
    const int g     = lane >> 2;
    const int t4    = lane & 3;
    const int wM    = warp >> 2;
    const int wN    = warp & 3;

    const float A  = -expf(A_log[h]);
    const float Dh = Dparam[h];

    // ---- cp.async staging of B, C (64x128 each) and X (64x64)
    #pragma unroll
    for (int j = 0; j < 8; j++) {
        int idx = j * 256 + tid;
        int t = idx >> 5, q = idx & 31;
        const float* row = convout + (r0 + t) * CONVDIM;
        cp16(smem_addr(Bs + t * 132 + q * 4), row + DINNER + q * 4, 16);
        cp16(smem_addr(Cs + t * 132 + q * 4), row + DINNER + DSTATE + q * 4, 16);
    }
    #pragma unroll
    for (int j = 0; j < 4; j++) {
        int idx = j * 256 + tid;
        int t = idx >> 4, q = idx & 15;
        cp16(smem_addr(Xs + t * 68 + q * 4),
             convout + (r0 + t) * CONVDIM + h * HEADDIM + q * 4, 16);
    }
    CP_COMMIT();

    if (tid < 64) {
        float d = dtbuf[(r0 + tid) * NHEADS + h];
        sdt[tid] = d;
        sS[tid]  = d;
    }
    __syncthreads();

    // ---- inclusive cumsum of dt (overlapped with cp.async in flight)
    #pragma unroll
    for (int off = 1; off < 64; off <<= 1) {
        float v = 0.f;
        if (tid < 64 && tid >= off) v = sS[tid - off];
        __syncthreads();
        if (tid < 64) sS[tid] += v;
        __syncthreads();
    }
    if (tid < 64) {
        float St = sS[tid], ST = sS[63];
        swS[tid] = sdt[tid] * __expf(A * (ST - St));
        etbuf[(size_t)ci * T_CH + tid] = __expf(A * St);
    }
    if (tid == 0) cdec[ci] = __expf(A * sS[63]);

    CP_WAIT(0);
    __syncthreads();

    // ---- Gram G[t][s] = sum_n C[t][n] B[s][n]
    float acc[2][2][4];
    #pragma unroll
    for (int mi = 0; mi < 2; mi++)
        #pragma unroll
        for (int ni = 0; ni < 2; ni++)
            #pragma unroll
            for (int r = 0; r < 4; r++) acc[mi][ni][r] = 0.f;

    #pragma unroll
    for (int ks = 0; ks < 16; ks++) {
        const int kk = ks * 8;
        uint32_t af[2][4], bf[2][2];
        #pragma unroll
        for (int mi = 0; mi < 2; mi++) {
            int m = wM * 32 + mi * 16;
            af[mi][0] = __float_as_uint(Cs[(m + g)     * 132 + kk + t4]);
            af[mi][1] = __float_as_uint(Cs[(m + g + 8) * 132 + kk + t4]);
            af[mi][2] = __float_as_uint(Cs[(m + g)     * 132 + kk + t4 + 4]);
            af[mi][3] = __float_as_uint(Cs[(m + g + 8) * 132 + kk + t4 + 4]);
        }
        #pragma unroll
        for (int ni = 0; ni < 2; ni++) {
            int s = wN * 16 + ni * 8 + g;
            bf[ni][0] = __float_as_uint(Bs[s * 132 + kk + t4]);
            bf[ni][1] = __float_as_uint(Bs[s * 132 + kk + t4 + 4]);
        }
        #pragma unroll
        for (int mi = 0; mi < 2; mi++)
            #pragma unroll
            for (int ni = 0; ni < 2; ni++)
                MMA_TF32(acc[mi][ni], af[mi][0], af[mi][1], af[mi][2],
                         af[mi][3], bf[ni][0], bf[ni][1]);
    }
    __syncthreads();   // Cs reads complete before Ms overwrite

    // ---- mask + decay-weight -> Ms[t][s]
    #pragma unroll
    for (int mi = 0; mi < 2; mi++) {
        #pragma unroll
        for (int ni = 0; ni < 2; ni++) {
            int tb = wM * 32 + mi * 16;
            int sb = wN * 16 + ni * 8 + 2 * t4;
            #pragma unroll
            for (int r = 0; r < 4; r++) {
                int tt = tb + g + ((r >= 2) ? 8 : 0);
                int ss = sb + (r & 1);
                float w = 0.f;
                if (ss <= tt) w = sdt[ss] * __expf(A * (sS[tt] - sS[ss]));
                Ms[tt * 68 + ss] = tfr(acc[mi][ni][r] * w);
            }
        }
    }
    // ---- Xw[p][t] = swS_t * x[t][p]
    #pragma unroll
    for (int j = 0; j < 16; j++) {
        int idx = j * 256 + tid;
        int p = idx >> 6, t = idx & 63;
        Xw[p * 68 + t] = tfr(swS[t] * Xs[t * 68 + p]);
    }
    __syncthreads();

    // ---- Y_intra = M . X
    float acc2[2][2][4];
    #pragma unroll
    for (int mi = 0; mi < 2; mi++)
        #pragma unroll
        for (int ni = 0; ni < 2; ni++)
            #pragma unroll
            for (int r = 0; r < 4; r++) acc2[mi][ni][r] = 0.f;

    #pragma unroll
    for (int ks = 0; ks < 8; ks++) {
        const int kk = ks * 8;
        uint32_t af[2][4], bf[2][2];
        #pragma unroll
        for (int mi = 0; mi < 2; mi++) {
            int m = wM * 32 + mi * 16;
            af[mi][0] = __float_as_uint(Ms[(m + g)     * 68 + kk + t4]);
            af[mi][1] = __float_as_uint(Ms[(m + g + 8) * 68 + kk + t4]);
            af[mi][2] = __float_as_uint(Ms[(m + g)     * 68 + kk + t4 + 4]);
            af[mi][3] = __float_as_uint(Ms[(m + g + 8) * 68 + kk + t4 + 4]);
        }
        #pragma unroll
        for (int ni = 0; ni < 2; ni++) {
            int p = wN * 16 + ni * 8 + g;
            bf[ni][0] = __float_as_uint(Xs[(kk + t4)     * 68 + p]);
            bf[ni][1] = __float_as_uint(Xs[(kk + t4 + 4) * 68 + p]);
        }
        #pragma unroll
        for (int mi = 0; mi < 2; mi++)
            #pragma unroll
            for (int ni = 0; ni < 2; ni++)
                MMA_TF32(acc2[mi][ni], af[mi][0], af[mi][1], af[mi][2],
                         af[mi][3], bf[ni][0], bf[ni][1]);
    }
    #pragma unroll
    for (int mi = 0; mi < 2; mi++) {
        #pragma unroll
        for (int ni = 0; ni < 2; ni++) {
            int tb = wM * 32 + mi * 16;
            int pb = wN * 16 + ni * 8 + 2 * t4;
            int t0 = tb + g, t1 = tb + g + 8;
            float2 o0 = make_float2(
                acc2[mi][ni][0] + Dh * Xs[t0 * 68 + pb],
                acc2[mi][ni][1] + Dh * Xs[t0 * 68 + pb + 1]);
            float2 o1 = make_float2(
                acc2[mi][ni][2] + Dh * Xs[t1 * 68 + pb],
                acc2[mi][ni][3] + Dh * Xs[t1 * 68 + pb + 1]);
            *(float2*)(y + (r0 + t0) * DINNER + h * HEADDIM + pb) = o0;
            *(float2*)(y + (r0 + t1) * DINNER + h * HEADDIM + pb) = o1;
        }
    }

    // ---- SI[p][n] = sum_t Xw[p][t] B[t][n]
    float acc3[2][4][4];
    #pragma unroll
    for (int mi = 0; mi < 2; mi++)
        #pragma unroll
        for (int ni = 0; ni < 4; ni++)
            #pragma unroll
            for (int r = 0; r < 4; r++) acc3[mi][ni][r] = 0.f;

    #pragma unroll
    for (int ks = 0; ks < 8; ks++) {
        const int kk = ks * 8;
        uint32_t af[2][4], bf[4][2];
        #pragma unroll
        for (int mi = 0; mi < 2; mi++) {
            int p = wM * 32 + mi * 16;
            af[mi][0] = __float_as_uint(Xw[(p + g)     * 68 + kk + t4]);
            af[mi][1] = __float_as_uint(Xw[(p + g + 8) * 68 + kk + t4]);
            af[mi][2] = __float_as_uint(Xw[(p + g)     * 68 + kk + t4 + 4]);
            af[mi][3] = __float_as_uint(Xw[(p + g + 8) * 68 + kk + t4 + 4]);
        }
        #pragma unroll
        for (int ni = 0; ni < 4; ni++) {
            int n = wN * 32 + ni * 8 + g;
            bf[ni][0] = __float_as_uint(Bs[(kk + t4)     * 132 + n]);
            bf[ni][1] = __float_as_uint(Bs[(kk + t4 + 4) * 132 + n]);
        }
        #pragma unroll
        for (int mi = 0; mi < 2; mi++)
            #pragma unroll
            for (int ni = 0; ni < 4; ni++)
                MMA_TF32(acc3[mi][ni], af[mi][0], af[mi][1], af[mi][2],
                         af[mi][3], bf[ni][0], bf[ni][1]);
    }
    #pragma unroll
    for (int mi = 0; mi < 2; mi++) {
        #pragma unroll
        for (int ni = 0; ni < 4; ni++) {
            int pb = wM * 32 + mi * 16;
            int nb = wN * 32 + ni * 8 + 2 * t4;
            size_t base = (size_t)ci * (HEADDIM * DSTATE);
            *(float2*)(sinc + base + (pb + g)     * DSTATE + nb) =
                make_float2(acc3[mi][ni][0], acc3[mi][ni][1]);
            *(float2*)(sinc + base + (pb + g + 8) * DSTATE + nb) =
                make_float2(acc3[mi][ni][2], acc3[mi][ni][3]);
        }
    }
}

// ---------------------------------------------------------------------------
// Inter-chunk sequential recurrence; state0 stored tf32-rounded.
// ---------------------------------------------------------------------------
__global__ __launch_bounds__(256)
void seq_kernel(const float* __restrict__ sinc,
                const float* __restrict__ cdec,
                float* __restrict__ state0)
{
    int bh = blockIdx.x;
    int b = bh >> 5, h = bh & 31;
    int tid = threadIdx.x;

    float st[32];
    #pragma unroll
    for (int j = 0; j < 32; j++) st[j] = 0.f;

    for (int k = 0; k < NCHUNK; k++) {
        int ci = b * (NHEADS * NCHUNK) + h * NCHUNK + k;
        float cd = cdec[ci];
        size_t base = (size_t)ci * (HEADDIM * DSTATE);
        #pragma unroll
        for (int j = 0; j < 32; j++) {
            size_t e = base + (size_t)j * 256 + tid;
            state0[e] = tfr(st[j]);
            st[j] = fmaf(st[j], cd, sinc[e]);
        }
    }
}

// ---------------------------------------------------------------------------
// Apply inter-chunk state: y[t][p] += e^{A S_t} * sum_n C[t][n] state0[p][n]
// S0 staged in native [p][n] layout via cp.async; bank = 4g+t4 (bijective).
// ---------------------------------------------------------------------------
#define AP_SMEM ((64*132 + 64*132 + 64) * 4)

__global__ __launch_bounds__(256)
void apply_kernel(const float* __restrict__ convout,
                  const float* __restrict__ state0,
                  const float* __restrict__ etbuf,
                  float* __restrict__ y)
{
    extern __shared__ float sm[];
    float* Cs  = sm;                  // [64][132]  C[t][n]
    float* S0s = Cs + 64 * 132;       // [64][132]  S0[p][n]
    float* set = S0s + 64 * 132;      // 64

    const int ci    = blockIdx.x;
    const int chunk = ci & (NCHUNK - 1);
    const int h     = (ci >> 6) & (NHEADS - 1);
    const int b     = ci >> 11;
    const long r0   = (long)b * SEQLEN + chunk * T_CH;
    const int tid   = threadIdx.x;
    const int warp  = tid >> 5;
    const int lane  = tid & 31;
    const int g     = lane >> 2;
    const int t4    = lane & 3;
    const int wM    = warp >> 2;
    const int wN    = warp & 3;

    const size_t sbase = (size_t)ci * (HEADDIM * DSTATE);
    #pragma unroll
    for (int j = 0; j < 8; j++) {
        int idx = j * 256 + tid;
        int t = idx >> 5, q = idx & 31;
        cp16(smem_addr(Cs + t * 132 + q * 4),
             convout + (r0 + t) * CONVDIM + DINNER + DSTATE + q * 4, 16);
        cp16(smem_addr(S0s + t * 132 + q * 4),
             state0 + sbase + (size_t)t * DSTATE + q * 4, 16);
    }
    CP_COMMIT();
    if (tid < 64) set[tid] = etbuf[(size_t)ci * T_CH + tid];
    CP_WAIT(0);
    __syncthreads();

    float acc[2][2][4];
    #pragma unroll
    for (int mi = 0; mi < 2; mi++)
        #pragma unroll
        for (int ni = 0; ni < 2; ni++)
            #pragma unroll
            for (int r = 0; r < 4; r++) acc[mi][ni][r] = 0.f;

    #pragma unroll
    for (int ks = 0; ks < 16; ks++) {
        const int kk = ks * 8;
        uint32_t af[2][4], bf[2][2];
        #pragma unroll
        for (int mi = 0; mi < 2; mi++) {
            int m = wM * 32 + mi * 16;
            af[mi][0] = __float_as_uint(Cs[(m + g)     * 132 + kk + t4]);
            af[mi][1] = __float_as_uint(Cs[(m + g + 8) * 132 + kk + t4]);
            af[mi][2] = __float_as_uint(Cs[(m + g)     * 132 + kk + t4 + 4]);
            af[mi][3] = __float_as_uint(Cs[(m + g + 8) * 132 + kk + t4 + 4]);
        }
        #pragma unroll
        for (int ni = 0; ni < 2; ni++) {
            int p = wN * 16 + ni * 8 + g;
            bf[ni][0] = __float_as_uint(S0s[p * 132 + kk + t4]);
            bf[ni][1] = __float_as_uint(S0s[p * 132 + kk + t4 + 4]);
        }
        #pragma unroll
        for (int mi = 0; mi < 2; mi++)
            #pragma unroll
            for (int ni = 0; ni < 2; ni++)
                MMA_TF32(acc[mi][ni], af[mi][0], af[mi][1], af[mi][2],
                         af[mi][3], bf[ni][0], bf[ni][1]);
    }

    #pragma unroll
    for (int mi = 0; mi < 2; mi++) {
        #pragma unroll
        for (int ni = 0; ni < 2; ni++) {
            int tb = wM * 32 + mi * 16;
            int pb = wN * 16 + ni * 8 + 2 * t4;
            int t0 = tb + g, t1 = tb + g + 8;
            float e0 = set[t0], e1 = set[t1];
            float2* a0 = (float2*)(y + (r0 + t0) * DINNER + h * HEADDIM + pb);
            float2* a1 = (float2*)(y + (r0 + t1) * DINNER + h * HEADDIM + pb);
            float2 v0 = *a0, v1 = *a1;
            v0.x += e0 * acc[mi][ni][0]; v0.y += e0 * acc[mi][ni][1];
            v1.x += e1 * acc[mi][ni][2]; v1.y += e1 * acc[mi][ni][3];
            *a0 = v0; *a1 = v1;
        }
    }
}

// ---------------------------------------------------------------------------
// Gated RMSNorm in place on y; output tf32-rounded.
// ---------------------------------------------------------------------------
__global__ __launch_bounds__(256)
void gated_rmsnorm_kernel(float* __restrict__ y,
                          const float* __restrict__ zxbcdt,
                          const float* __restrict__ norm_w)
{
    long r = blockIdx.x;
    int tid = threadIdx.x;
    float* yr = y + r * DINNER;
    const float* zr = zxbcdt + r * DINPROJ;

    float vals[8];
    float ss = 0.f;
    #pragma unroll
    for (int i = 0; i < 8; i++) {
        int c = tid + i * 256;
        float z  = zr[c];
        float gv = yr[c] * (z / (1.f + expf(-z)));
        vals[i] = gv;
        ss = fmaf(gv, gv, ss);
    }

    __shared__ float sred[256];
    sred[tid] = ss;
    __syncthreads();
    #pragma unroll
    for (int off = 128; off > 0; off >>= 1) {
        if (tid < off) sred[tid] += sred[tid + off];
        __syncthreads();
    }
    float scale = rsqrtf(sred[0] / (float)DINNER + 1e-5f);

    #pragma unroll
    for (int i = 0; i < 8; i++) {
        int c = tid + i * 256;
        yr[c] = tfr(vals[i] * scale * norm_w[c]);
    }
}

// ---------------------------------------------------------------------------
// Launch. Inputs: x, in_proj_w, conv_w, conv_b, norm_w, out_proj_w,
//                 dt_bias, A_log, D
// ---------------------------------------------------------------------------
extern "C" void kernel_launch(void* const* d_in, const int* in_sizes, int n_in,
                              void* d_out, int out_size)
{
    const float* x          = (const float*)d_in[0];
    const float* in_proj_w  = (const float*)d_in[1];
    const float* conv_w     = (const float*)d_in[2];
    const float* conv_b     = (const float*)d_in[3];
    const float* norm_w     = (const float*)d_in[4];
    const float* out_proj_w = (const float*)d_in[5];
    const float* dt_bias    = (const float*)d_in[6];
    const float* A_log      = (const float*)d_in[7];
    const float* Dparam     = (const float*)d_in[8];
    float* out = (float*)d_out;

    float *zxbcdt, *convbuf, *ybuf, *xtf, *w1tf, *w2tf, *dtb;
    float *sincb, *state0b, *etb, *cdecb;
    cudaGetSymbolAddress((void**)&zxbcdt,  g_zxbcdt);
    cudaGetSymbolAddress((void**)&convbuf, g_conv);
    cudaGetSymbolAddress((void**)&ybuf,    g_y);
    cudaGetSymbolAddress((void**)&xtf,     g_xtf);
    cudaGetSymbolAddress((void**)&w1tf,    g_w1tf);
    cudaGetSymbolAddress((void**)&w2tf,    g_w2tf);
    cudaGetSymbolAddress((void**)&dtb,     g_dt);
    cudaGetSymbolAddress((void**)&sincb,   g_sinc);
    cudaGetSymbolAddress((void**)&state0b, g_state0);
    cudaGetSymbolAddress((void**)&etb,     g_et);
    cudaGetSymbolAddress((void**)&cdecb,   g_cdec);

    cudaFuncSetAttribute(tf32_gemm_kernel,
                         cudaFuncAttributeMaxDynamicSharedMemorySize, GEMM_SMEM);
    cudaFuncSetAttribute(chunk_kernel,
                         cudaFuncAttributeMaxDynamicSharedMemorySize, CH_SMEM);
    cudaFuncSetAttribute(apply_kernel,
                         cudaFuncAttributeMaxDynamicSharedMemorySize, AP_SMEM);

    // 0) tf32 rounding pre-passes
    {
        long n4;
        n4 = (long)ROWS * DMODEL / 4;
        cvt_tf32_kernel<<<(unsigned)((n4 + 255) / 256), 256>>>(x, xtf, n4);
        n4 = (long)DMODEL * DINPROJ / 4;
        cvt_tf32_kernel<<<(unsigned)((n4 + 255) / 256), 256>>>(in_proj_w, w1tf, n4);
        n4 = (long)DINNER * DMODEL / 4;
        cvt_tf32_kernel<<<(unsigned)((n4 + 255) / 256), 256>>>(out_proj_w, w2tf, n4);
    }

    // 1) in_proj
    {
        dim3 grid((DINPROJ + 127) / 128, ROWS / 128);
        tf32_gemm_kernel<<<grid, 256, GEMM_SMEM>>>(xtf, w1tf, zxbcdt,
                                                   ROWS, DINPROJ, DMODEL);
    }

    // 2) conv + silu (8 timesteps per thread, tf32-rounded output)
    {
        dim3 grid(CONVDIM / 256, ROWS / 8);
        conv_silu_kernel<<<grid, 256>>>(zxbcdt, conv_w, conv_b, convbuf);
    }

    // 3) dt precompute
    {
        long total = (long)ROWS * NHEADS;
        dt_kernel<<<(unsigned)((total + 255) / 256), 256>>>(zxbcdt, dt_bias, dtb);
    }

    // 4) chunked scan
    chunk_kernel<<<NCTA_CH, 256, CH_SMEM>>>(convbuf, dtb, A_log, Dparam,
                                            ybuf, sincb, etb, cdecb);

    // 5) inter-chunk recurrence
    seq_kernel<<<BATCH * NHEADS, 256>>>(sincb, cdecb, state0b);

    // 6) apply chunk-start states
    apply_kernel<<<NCTA_CH, 256, AP_SMEM>>>(convbuf, state0b, etb, ybuf);

    // 7) gated RMSNorm
    gated_rmsnorm_kernel<<<ROWS, 256>>>(ybuf, zxbcdt, norm_w);

    // 8) out_proj
    {
        dim3 grid(DMODEL / 128, ROWS / 128);
        tf32_gemm_kernel<<<grid, 256, GEMM_SMEM>>>(ybuf, w2tf, out,
                                                   ROWS, DMODEL, DINNER);
    }
}

// round 12
// speedup vs baseline: 1.0777x; 1.0079x over previous
#include <cuda_runtime.h>
#include <cuda_bf16.h>
#include <math.h>
#include <stdint.h>

// ---------------------------------------------------------------------------
// Problem constants (Mamba2 block)
// ---------------------------------------------------------------------------
#define BATCH     2
#define SEQLEN    4096
#define DMODEL    1024
#define DSTATE    128
#define DCONV     4
#define HEADDIM   64
#define DINNER    2048
#define NHEADS    32
#define CONVDIM   2304              // DINNER + 2*DSTATE
#define DINPROJ   4384              // 2*DINNER + 2*DSTATE + NHEADS
#define ROWS      (BATCH*SEQLEN)    // 8192
#define DTCOL     (2*DINNER + 2*DSTATE)   // 4352

#define T_CH      64
#define NCHUNK    (SEQLEN / T_CH)   // 64
#define NCTA_CH   (BATCH * NHEADS * NCHUNK)   // 4096

// Scratch (allocation-free rule: __device__ globals)
__device__ float g_zxbcdt[(size_t)ROWS * DINPROJ];
__device__ float g_conv  [(size_t)ROWS * CONVDIM];   // tf32-rounded conv+silu
__device__ float g_y     [(size_t)ROWS * DINNER];
__device__ float g_xtf   [(size_t)ROWS * DMODEL];
__device__ float g_w1tf  [(size_t)DMODEL * DINPROJ];
__device__ float g_w2tf  [(size_t)DINNER * DMODEL];
__device__ float g_dt    [(size_t)ROWS * NHEADS];
__device__ float g_sinc  [(size_t)NCTA_CH * HEADDIM * DSTATE];
__device__ float g_state0[(size_t)NCTA_CH * HEADDIM * DSTATE];  // tf32-rounded
__device__ float g_et    [(size_t)NCTA_CH * T_CH];
__device__ float g_cdec  [(size_t)NCTA_CH];

__device__ __forceinline__ uint32_t f2tf32(float f) {
    uint32_t r;
    asm("cvt.rna.tf32.f32 %0, %1;" : "=r"(r) : "f"(f));
    return r;
}
__device__ __forceinline__ float tfr(float f) {
    return __uint_as_float(f2tf32(f));
}
__device__ __forceinline__ uint32_t smem_addr(const void* p) {
    return (uint32_t)__cvta_generic_to_shared(p);
}
__device__ __forceinline__ void cp16(uint32_t dst, const void* src, int sz) {
    asm volatile("cp.async.cg.shared.global [%0], [%1], 16, %2;"
                 :: "r"(dst), "l"(src), "r"(sz) : "memory");
}
#define CP_COMMIT() asm volatile("cp.async.commit_group;" ::: "memory")
#define CP_WAIT(n)  asm volatile("cp.async.wait_group %0;" :: "n"(n) : "memory")

#define MMA_TF32(acc, a0, a1, a2, a3, b0, b1)                               \
    asm volatile(                                                           \
        "mma.sync.aligned.m16n8k8.row.col.f32.tf32.tf32.f32 "               \
        "{%0,%1,%2,%3}, {%4,%5,%6,%7}, {%8,%9}, {%0,%1,%2,%3};"             \
        : "+f"((acc)[0]), "+f"((acc)[1]), "+f"((acc)[2]), "+f"((acc)[3])    \
        : "r"(a0), "r"(a1), "r"(a2), "r"(a3), "r"(b0), "r"(b1))

// ---------------------------------------------------------------------------
// Elementwise tf32 rounding pre-pass
// ---------------------------------------------------------------------------
__global__ void cvt_tf32_kernel(const float* __restrict__ in,
                                float* __restrict__ out, long n4)
{
    long i = (long)blockIdx.x * blockDim.x + threadIdx.x;
    if (i >= n4) return;
    float4 v = ((const float4*)in)[i];
    float4 o = make_float4(tfr(v.x), tfr(v.y), tfr(v.z), tfr(v.w));
    ((float4*)out)[i] = o;
}

// ---------------------------------------------------------------------------
// TF32 mma.sync GEMM, 3-stage cp.async pipeline (128x128 tile, 2 CTA/SM)
// ---------------------------------------------------------------------------
#define GSTAGES 3
#define ASTR 36
#define BSTR 136
#define STAGE_WORDS (128*ASTR + 32*BSTR)
#define GEMM_SMEM   (GSTAGES * STAGE_WORDS * 4)

__global__ __launch_bounds__(256, 2)
void tf32_gemm_kernel(const float* __restrict__ A, const float* __restrict__ B,
                      float* __restrict__ C, int M, int N, int K)
{
    extern __shared__ uint32_t smem[];

    const int tid   = threadIdx.x;
    const int warp  = tid >> 5;
    const int lane  = tid & 31;
    const int g     = lane >> 2;
    const int t4    = lane & 3;
    const int warpM = warp >> 2;
    const int warpN = warp & 3;
    const int rowC  = blockIdx.y * 128;
    const int colC  = blockIdx.x * 128;
    const int NC    = K / 32;

    auto stage_cp = [&](int chunk, int slot) {
        uint32_t* As = smem + slot * STAGE_WORDS;
        uint32_t* Bs = As + 128 * ASTR;
        const int k0 = chunk * 32;
        #pragma unroll
        for (int p = 0; p < 4; p++) {
            int i = p * 256 + tid;
            int m = i >> 3, kq = i & 7;
            cp16(smem_addr(As + m * ASTR + kq * 4),
                 A + (size_t)(rowC + m) * K + k0 + kq * 4, 16);
        }
        #pragma unroll
        for (int p = 0; p < 4; p++) {
            int i = p * 256 + tid;
            int kl = i >> 5, nq = i & 31;
            int gcol = colC + nq * 4;
            int ok = (gcol < N);
            cp16(smem_addr(Bs + kl * BSTR + nq * 4),
                 B + (size_t)(k0 + kl) * N + (ok ? gcol : 0), ok ? 16 : 0);
        }
    };

    float acc[4][4][4];
    #pragma unroll
    for (int mi = 0; mi < 4; mi++)
        #pragma unroll
        for (int ni = 0; ni < 4; ni++)
            #pragma unroll
            for (int r = 0; r < 4; r++) acc[mi][ni][r] = 0.f;

    stage_cp(0, 0); CP_COMMIT();
    stage_cp(1, 1); CP_COMMIT();

    for (int i = 0; i < NC; i++) {
        if (i < NC - 1) CP_WAIT(1); else CP_WAIT(0);
        __syncthreads();
        if (i + 2 < NC) { stage_cp(i + 2, (i + 2) % GSTAGES); CP_COMMIT(); }

        const uint32_t* As = smem + (i % GSTAGES) * STAGE_WORDS;
        const uint32_t* Bs = As + 128 * ASTR;

        #pragma unroll
        for (int ks = 0; ks < 4; ks++) {
            const int kk = ks * 8;
            uint32_t af[4][4];
            #pragma unroll
            for (int mi = 0; mi < 4; mi++) {
                int m = warpM * 64 + mi * 16;
                af[mi][0] = As[(m + g)     * ASTR + kk + t4];
                af[mi][1] = As[(m + g + 8) * ASTR + kk + t4];
                af[mi][2] = As[(m + g)     * ASTR + kk + t4 + 4];
                af[mi][3] = As[(m + g + 8) * ASTR + kk + t4 + 4];
            }
            uint32_t bf[4][2];
            #pragma unroll
            for (int ni = 0; ni < 4; ni++) {
                int n = warpN * 32 + ni * 8 + g;
                bf[ni][0] = Bs[(kk + t4)     * BSTR + n];
                bf[ni][1] = Bs[(kk + t4 + 4) * BSTR + n];
            }
            #pragma unroll
            for (int mi = 0; mi < 4; mi++)
                #pragma unroll
                for (int ni = 0; ni < 4; ni++)
                    MMA_TF32(acc[mi][ni], af[mi][0], af[mi][1], af[mi][2],
                             af[mi][3], bf[ni][0], bf[ni][1]);
        }
    }

    #pragma unroll
    for (int mi = 0; mi < 4; mi++) {
        int r0 = rowC + warpM * 64 + mi * 16 + g;
        #pragma unroll
        for (int ni = 0; ni < 4; ni++) {
            int cc = colC + warpN * 32 + ni * 8 + t4 * 2;
            if (cc < N) {
                *(float2*)(C + (size_t)r0 * N + cc)       =
                    make_float2(acc[mi][ni][0], acc[mi][ni][1]);
                *(float2*)(C + (size_t)(r0 + 8) * N + cc) =
                    make_float2(acc[mi][ni][2], acc[mi][ni][3]);
            }
        }
    }
}

// ---------------------------------------------------------------------------
// Causal depthwise conv1d (K=4) + SiLU, sliding-window, 8 timesteps/thread.
// ---------------------------------------------------------------------------
__global__ __launch_bounds__(256)
void conv_silu_kernel(const float* __restrict__ zxbcdt,
                      const float* __restrict__ conv_w,
                      const float* __restrict__ conv_b,
                      float* __restrict__ out)
{
    const int  c  = blockIdx.x * 256 + threadIdx.x;
    const long r0 = (long)blockIdx.y * 8;
    const int  l0 = (int)(r0 & (SEQLEN - 1));

    const float w0 = conv_w[0 * CONVDIM + c];
    const float w1 = conv_w[1 * CONVDIM + c];
    const float w2 = conv_w[2 * CONVDIM + c];
    const float w3 = conv_w[3 * CONVDIM + c];
    const float bias = conv_b[c];

    const float* base = zxbcdt + r0 * DINPROJ + DINNER + c;
    float xm3 = 0.f, xm2 = 0.f, xm1 = 0.f;
    if (l0 > 0) {
        xm3 = base[-3 * (long)DINPROJ];
        xm2 = base[-2 * (long)DINPROJ];
        xm1 = base[-1 * (long)DINPROJ];
    }
    float* orow = out + r0 * CONVDIM + c;
    #pragma unroll
    for (int i = 0; i < 8; i++) {
        float x0 = base[(long)i * DINPROJ];
        float acc = bias + w0 * x0 + w1 * xm1 + w2 * xm2 + w3 * xm3;
        float s = acc / (1.f + __expf(-acc));
        orow[(long)i * CONVDIM] = tfr(s);
        xm3 = xm2; xm2 = xm1; xm1 = x0;
    }
}

// ---------------------------------------------------------------------------
// dt precompute: dt = softplus(dt_raw + bias)
// ---------------------------------------------------------------------------
__global__ void dt_kernel(const float* __restrict__ zxbcdt,
                          const float* __restrict__ dt_bias,
                          float* __restrict__ dt_out)
{
    long idx = (long)blockIdx.x * blockDim.x + threadIdx.x;
    if (idx >= (long)ROWS * NHEADS) return;
    int  h = (int)(idx & (NHEADS - 1));
    long r = idx >> 5;
    float v  = zxbcdt[r * DINPROJ + DTCOL + h] + dt_bias[h];
    dt_out[idx] = (v > 20.f) ? v : log1pf(__expf(v));
}

// ---------------------------------------------------------------------------
// Chunked scan, intra-chunk kernel. Decay mask via OUTER PRODUCT:
//   dt_s * e^{A(S_t - S_s)} = wrow[t] * wcol[s],
//   wrow[t] = e^{A(S_t - Smid)},  wcol[s] = dt_s * e^{-A(S_s - Smid)}
// (mid-centered; exponent magnitude <= |A| * S_range/2, no fp32 overflow)
// -> 128 expf/CTA instead of 4096 (MUFU was the chunk bottleneck).
// ---------------------------------------------------------------------------
#define CH_SMEM ((64*132 + 64*132 + 64*68 + 64*68 + 6*64) * 4)

__global__ __launch_bounds__(256, 2)
void chunk_kernel(const float* __restrict__ convout,
                  const float* __restrict__ dtbuf,
                  const float* __restrict__ A_log,
                  const float* __restrict__ Dparam,
                  float* __restrict__ y,
                  float* __restrict__ sinc,
                  float* __restrict__ etbuf,
                  float* __restrict__ cdec)
{
    extern __shared__ float sm[];
    float* Bs  = sm;                  // [64][132]  B[t][n]
    float* Cs  = Bs + 64 * 132;       // [64][132]  C[t][n]; reused as Ms
    float* Xs  = Cs + 64 * 132;       // [64][68]   x[t][p]
    float* Xw  = Xs + 64 * 68;        // [64][68]   weighted x^T [p][t]
    float* sS   = Xw + 64 * 68;       // 64  inclusive cumsum of dt
    float* sdt  = sS + 64;            // 64
    float* swS  = sdt + 64;           // 64  dt_t * e^{A(S_T - S_t)}
    float* wrow = swS + 64;           // 64  e^{A(S_t - Smid)}
    float* wcol = wrow + 64;          // 64  dt_s * e^{-A(S_s - Smid)}
    float* Ms  = Cs;

    const int ci    = blockIdx.x;
    const int chunk = ci & (NCHUNK - 1);
    const int h     = (ci >> 6) & (NHEADS - 1);
    const int b     = ci >> 11;
    const long r0   = (long)b * SEQLEN + chunk * T_CH;
    const int tid   = threadIdx.x;
    const int warp  = tid >> 5;
    const int lane  = tid & 31;
    const int g     = lane >> 2;
    const int t4    = lane & 3;
    const int wM    = warp >> 2;
    const int wN    = warp & 3;

    const float A  = -__expf(A_log[h]);
    const float Dh = Dparam[h];

    // ---- cp.async staging of B, C (64x128 each) and X (64x64)
    #pragma unroll
    for (int j = 0; j < 8; j++) {
        int idx = j * 256 + tid;
        int t = idx >> 5, q = idx & 31;
        const float* row = convout + (r0 + t) * CONVDIM;
        cp16(smem_addr(Bs + t * 132 + q * 4), row + DINNER + q * 4, 16);
        cp16(smem_addr(Cs + t * 132 + q * 4), row + DINNER + DSTATE + q * 4, 16);
    }
    #pragma unroll
    for (int j = 0; j < 4; j++) {
        int idx = j * 256 + tid;
        int t = idx >> 4, q = idx & 15;
        cp16(smem_addr(Xs + t * 68 + q * 4),
             convout + (r0 + t) * CONVDIM + h * HEADDIM + q * 4, 16);
    }
    CP_COMMIT();

    if (tid < 64) {
        float d = dtbuf[(r0 + tid) * NHEADS + h];
        sdt[tid] = d;
        sS[tid]  = d;
    }
    __syncthreads();

    // ---- inclusive cumsum of dt
    #pragma unroll
    for (int off = 1; off < 64; off <<= 1) {
        float v = 0.f;
        if (tid < 64 && tid >= off) v = sS[tid - off];
        __syncthreads();
        if (tid < 64) sS[tid] += v;
        __syncthreads();
    }
    if (tid < 64) {
        float St   = sS[tid];
        float ST   = sS[63];
        float Smid = sS[31];
        swS[tid]  = sdt[tid] * __expf(A * (ST - St));
        wrow[tid] = __expf(A * (St - Smid));
        wcol[tid] = sdt[tid] * __expf(-A * (St - Smid));
        etbuf[(size_t)ci * T_CH + tid] = __expf(A * St);
    }
    if (tid == 0) cdec[ci] = __expf(A * sS[63]);

    CP_WAIT(0);
    __syncthreads();

    // ---- Gram G[t][s] = sum_n C[t][n] B[s][n]
    float acc[2][2][4];
    #pragma unroll
    for (int mi = 0; mi < 2; mi++)
        #pragma unroll
        for (int ni = 0; ni < 2; ni++)
            #pragma unroll
            for (int r = 0; r < 4; r++) acc[mi][ni][r] = 0.f;

    #pragma unroll
    for (int ks = 0; ks < 16; ks++) {
        const int kk = ks * 8;
        uint32_t af[2][4], bf[2][2];
        #pragma unroll
        for (int mi = 0; mi < 2; mi++) {
            int m = wM * 32 + mi * 16;
            af[mi][0] = __float_as_uint(Cs[(m + g)     * 132 + kk + t4]);
            af[mi][1] = __float_as_uint(Cs[(m + g + 8) * 132 + kk + t4]);
            af[mi][2] = __float_as_uint(Cs[(m + g)     * 132 + kk + t4 + 4]);
            af[mi][3] = __float_as_uint(Cs[(m + g + 8) * 132 + kk + t4 + 4]);
        }
        #pragma unroll
        for (int ni = 0; ni < 2; ni++) {
            int s = wN * 16 + ni * 8 + g;
            bf[ni][0] = __float_as_uint(Bs[s * 132 + kk + t4]);
            bf[ni][1] = __float_as_uint(Bs[s * 132 + kk + t4 + 4]);
        }
        #pragma unroll
        for (int mi = 0; mi < 2; mi++)
            #pragma unroll
            for (int ni = 0; ni < 2; ni++)
                MMA_TF32(acc[mi][ni], af[mi][0], af[mi][1], af[mi][2],
                         af[mi][3], bf[ni][0], bf[ni][1]);
    }
    __syncthreads();   // Cs reads complete before Ms overwrite

    // ---- mask + decay-weight -> Ms[t][s] (outer product, no expf)
    #pragma unroll
    for (int mi = 0; mi < 2; mi++) {
        #pragma unroll
        for (int ni = 0; ni < 2; ni++) {
            int tb = wM * 32 + mi * 16;
            int sb = wN * 16 + ni * 8 + 2 * t4;
            #pragma unroll
            for (int r = 0; r < 4; r++) {
                int tt = tb + g + ((r >= 2) ? 8 : 0);
                int ss = sb + (r & 1);
                float w = (ss <= tt) ? wrow[tt] * wcol[ss] : 0.f;
                Ms[tt * 68 + ss] = tfr(acc[mi][ni][r] * w);
            }
        }
    }
    // ---- Xw[p][t] = swS_t * x[t][p]
    #pragma unroll
    for (int j = 0; j < 16; j++) {
        int idx = j * 256 + tid;
        int p = idx >> 6, t = idx & 63;
        Xw[p * 68 + t] = tfr(swS[t] * Xs[t * 68 + p]);
    }
    __syncthreads();

    // ---- Y_intra = M . X
    float acc2[2][2][4];
    #pragma unroll
    for (int mi = 0; mi < 2; mi++)
        #pragma unroll
        for (int ni = 0; ni < 2; ni++)
            #pragma unroll
            for (int r = 0; r < 4; r++) acc2[mi][ni][r] = 0.f;

    #pragma unroll
    for (int ks = 0; ks < 8; ks++) {
        const int kk = ks * 8;
        uint32_t af[2][4], bf[2][2];
        #pragma unroll
        for (int mi = 0; mi < 2; mi++) {
            int m = wM * 32 + mi * 16;
            af[mi][0] = __float_as_uint(Ms[(m + g)     * 68 + kk + t4]);
            af[mi][1] = __float_as_uint(Ms[(m + g + 8) * 68 + kk + t4]);
            af[mi][2] = __float_as_uint(Ms[(m + g)     * 68 + kk + t4 + 4]);
            af[mi][3] = __float_as_uint(Ms[(m + g + 8) * 68 + kk + t4 + 4]);
        }
        #pragma unroll
        for (int ni = 0; ni < 2; ni++) {
            int p = wN * 16 + ni * 8 + g;
            bf[ni][0] = __float_as_uint(Xs[(kk + t4)     * 68 + p]);
            bf[ni][1] = __float_as_uint(Xs[(kk + t4 + 4) * 68 + p]);
        }
        #pragma unroll
        for (int mi = 0; mi < 2; mi++)
            #pragma unroll
            for (int ni = 0; ni < 2; ni++)
                MMA_TF32(acc2[mi][ni], af[mi][0], af[mi][1], af[mi][2],
                         af[mi][3], bf[ni][0], bf[ni][1]);
    }
    #pragma unroll
    for (int mi = 0; mi < 2; mi++) {
        #pragma unroll
        for (int ni = 0; ni < 2; ni++) {
            int tb = wM * 32 + mi * 16;
            int pb = wN * 16 + ni * 8 + 2 * t4;
            int t0 = tb + g, t1 = tb + g + 8;
            float2 o0 = make_float2(
                acc2[mi][ni][0] + Dh * Xs[t0 * 68 + pb],
                acc2[mi][ni][1] + Dh * Xs[t0 * 68 + pb + 1]);
            float2 o1 = make_float2(
                acc2[mi][ni][2] + Dh * Xs[t1 * 68 + pb],
                acc2[mi][ni][3] + Dh * Xs[t1 * 68 + pb + 1]);
            *(float2*)(y + (r0 + t0) * DINNER + h * HEADDIM + pb) = o0;
            *(float2*)(y + (r0 + t1) * DINNER + h * HEADDIM + pb) = o1;
        }
    }

    // ---- SI[p][n] = sum_t Xw[p][t] B[t][n]
    float acc3[2][4][4];
    #pragma unroll
    for (int mi = 0; mi < 2; mi++)
        #pragma unroll
        for (int ni = 0; ni < 4; ni++)
            #pragma unroll
            for (int r = 0; r < 4; r++) acc3[mi][ni][r] = 0.f;

    #pragma unroll
    for (int ks = 0; ks < 8; ks++) {
        const int kk = ks * 8;
        uint32_t af[2][4], bf[4][2];
        #pragma unroll
        for (int mi = 0; mi < 2; mi++) {
            int p = wM * 32 + mi * 16;
            af[mi][0] = __float_as_uint(Xw[(p + g)     * 68 + kk + t4]);
            af[mi][1] = __float_as_uint(Xw[(p + g + 8) * 68 + kk + t4]);
            af[mi][2] = __float_as_uint(Xw[(p + g)     * 68 + kk + t4 + 4]);
            af[mi][3] = __float_as_uint(Xw[(p + g + 8) * 68 + kk + t4 + 4]);
        }
        #pragma unroll
        for (int ni = 0; ni < 4; ni++) {
            int n = wN * 32 + ni * 8 + g;
            bf[ni][0] = __float_as_uint(Bs[(kk + t4)     * 132 + n]);
            bf[ni][1] = __float_as_uint(Bs[(kk + t4 + 4) * 132 + n]);
        }
        #pragma unroll
        for (int mi = 0; mi < 2; mi++)
            #pragma unroll
            for (int ni = 0; ni < 4; ni++)
                MMA_TF32(acc3[mi][ni], af[mi][0], af[mi][1], af[mi][2],
                         af[mi][3], bf[ni][0], bf[ni][1]);
    }
    #pragma unroll
    for (int mi = 0; mi < 2; mi++) {
        #pragma unroll
        for (int ni = 0; ni < 4; ni++) {
            int pb = wM * 32 + mi * 16;
            int nb = wN * 32 + ni * 8 + 2 * t4;
            size_t base = (size_t)ci * (HEADDIM * DSTATE);
            *(float2*)(sinc + base + (pb + g)     * DSTATE + nb) =
                make_float2(acc3[mi][ni][0], acc3[mi][ni][1]);
            *(float2*)(sinc + base + (pb + g + 8) * DSTATE + nb) =
                make_float2(acc3[mi][ni][2], acc3[mi][ni][3]);
        }
    }
}

// ---------------------------------------------------------------------------
// Inter-chunk sequential recurrence; state0 stored tf32-rounded.
// ---------------------------------------------------------------------------
__global__ __launch_bounds__(256)
void seq_kernel(const float* __restrict__ sinc,
                const float* __restrict__ cdec,
                float* __restrict__ state0)
{
    int bh = blockIdx.x;
    int b = bh >> 5, h = bh & 31;
    int tid = threadIdx.x;

    float st[32];
    #pragma unroll
    for (int j = 0; j < 32; j++) st[j] = 0.f;

    for (int k = 0; k < NCHUNK; k++) {
        int ci = b * (NHEADS * NCHUNK) + h * NCHUNK + k;
        float cd = cdec[ci];
        size_t base = (size_t)ci * (HEADDIM * DSTATE);
        #pragma unroll
        for (int j = 0; j < 32; j++) {
            size_t e = base + (size_t)j * 256 + tid;
            state0[e] = tfr(st[j]);
            st[j] = fmaf(st[j], cd, sinc[e]);
        }
    }
}

// ---------------------------------------------------------------------------
// Apply inter-chunk state: y[t][p] += e^{A S_t} * sum_n C[t][n] state0[p][n]
// ---------------------------------------------------------------------------
#define AP_SMEM ((64*132 + 64*132 + 64) * 4)

__global__ __launch_bounds__(256)
void apply_kernel(const float* __restrict__ convout,
                  const float* __restrict__ state0,
                  const float* __restrict__ etbuf,
                  float* __restrict__ y)
{
    extern __shared__ float sm[];
    float* Cs  = sm;                  // [64][132]  C[t][n]
    float* S0s = Cs + 64 * 132;       // [64][132]  S0[p][n]
    float* set = S0s + 64 * 132;      // 64

    const int ci    = blockIdx.x;
    const int chunk = ci & (NCHUNK - 1);
    const int h     = (ci >> 6) & (NHEADS - 1);
    const int b     = ci >> 11;
    const long r0   = (long)b * SEQLEN + chunk * T_CH;
    const int tid   = threadIdx.x;
    const int warp  = tid >> 5;
    const int lane  = tid & 31;
    const int g     = lane >> 2;
    const int t4    = lane & 3;
    const int wM    = warp >> 2;
    const int wN    = warp & 3;

    const size_t sbase = (size_t)ci * (HEADDIM * DSTATE);
    #pragma unroll
    for (int j = 0; j < 8; j++) {
        int idx = j * 256 + tid;
        int t = idx >> 5, q = idx & 31;
        cp16(smem_addr(Cs + t * 132 + q * 4),
             convout + (r0 + t) * CONVDIM + DINNER + DSTATE + q * 4, 16);
        cp16(smem_addr(S0s + t * 132 + q * 4),
             state0 + sbase + (size_t)t * DSTATE + q * 4, 16);
    }
    CP_COMMIT();
    if (tid < 64) set[tid] = etbuf[(size_t)ci * T_CH + tid];
    CP_WAIT(0);
    __syncthreads();

    float acc[2][2][4];
    #pragma unroll
    for (int mi = 0; mi < 2; mi++)
        #pragma unroll
        for (int ni = 0; ni < 2; ni++)
            #pragma unroll
            for (int r = 0; r < 4; r++) acc[mi][ni][r] = 0.f;

    #pragma unroll
    for (int ks = 0; ks < 16; ks++) {
        const int kk = ks * 8;
        uint32_t af[2][4], bf[2][2];
        #pragma unroll
        for (int mi = 0; mi < 2; mi++) {
            int m = wM * 32 + mi * 16;
            af[mi][0] = __float_as_uint(Cs[(m + g)     * 132 + kk + t4]);
            af[mi][1] = __float_as_uint(Cs[(m + g + 8) * 132 + kk + t4]);
            af[mi][2] = __float_as_uint(Cs[(m + g)     * 132 + kk + t4 + 4]);
            af[mi][3] = __float_as_uint(Cs[(m + g + 8) * 132 + kk + t4 + 4]);
        }
        #pragma unroll
        for (int ni = 0; ni < 2; ni++) {
            int p = wN * 16 + ni * 8 + g;
            bf[ni][0] = __float_as_uint(S0s[p * 132 + kk + t4]);
            bf[ni][1] = __float_as_uint(S0s[p * 132 + kk + t4 + 4]);
        }
        #pragma unroll
        for (int mi = 0; mi < 2; mi++)
            #pragma unroll
            for (int ni = 0; ni < 2; ni++)
                MMA_TF32(acc[mi][ni], af[mi][0], af[mi][1], af[mi][2],
                         af[mi][3], bf[ni][0], bf[ni][1]);
    }

    #pragma unroll
    for (int mi = 0; mi < 2; mi++) {
        #pragma unroll
        for (int ni = 0; ni < 2; ni++) {
            int tb = wM * 32 + mi * 16;
            int pb = wN * 16 + ni * 8 + 2 * t4;
            int t0 = tb + g, t1 = tb + g + 8;
            float e0 = set[t0], e1 = set[t1];
            float2* a0 = (float2*)(y + (r0 + t0) * DINNER + h * HEADDIM + pb);
            float2* a1 = (float2*)(y + (r0 + t1) * DINNER + h * HEADDIM + pb);
            float2 v0 = *a0, v1 = *a1;
            v0.x += e0 * acc[mi][ni][0]; v0.y += e0 * acc[mi][ni][1];
            v1.x += e1 * acc[mi][ni][2]; v1.y += e1 * acc[mi][ni][3];
            *a0 = v0; *a1 = v1;
        }
    }
}

// ---------------------------------------------------------------------------
// Gated RMSNorm in place on y; output tf32-rounded.
// ---------------------------------------------------------------------------
__global__ __launch_bounds__(256)
void gated_rmsnorm_kernel(float* __restrict__ y,
                          const float* __restrict__ zxbcdt,
                          const float* __restrict__ norm_w)
{
    long r = blockIdx.x;
    int tid = threadIdx.x;
    float* yr = y + r * DINNER;
    const float* zr = zxbcdt + r * DINPROJ;

    float vals[8];
    float ss = 0.f;
    #pragma unroll
    for (int i = 0; i < 8; i++) {
        int c = tid + i * 256;
        float z  = zr[c];
        float gv = yr[c] * (z / (1.f + __expf(-z)));
        vals[i] = gv;
        ss = fmaf(gv, gv, ss);
    }

    __shared__ float sred[256];
    sred[tid] = ss;
    __syncthreads();
    #pragma unroll
    for (int off = 128; off > 0; off >>= 1) {
        if (tid < off) sred[tid] += sred[tid + off];
        __syncthreads();
    }
    float scale = rsqrtf(sred[0] / (float)DINNER + 1e-5f);

    #pragma unroll
    for (int i = 0; i < 8; i++) {
        int c = tid + i * 256;
        yr[c] = tfr(vals[i] * scale * norm_w[c]);
    }
}

// ---------------------------------------------------------------------------
// Launch. Inputs: x, in_proj_w, conv_w, conv_b, norm_w, out_proj_w,
//                 dt_bias, A_log, D
// ---------------------------------------------------------------------------
extern "C" void kernel_launch(void* const* d_in, const int* in_sizes, int n_in,
                              void* d_out, int out_size)
{
    const float* x          = (const float*)d_in[0];
    const float* in_proj_w  = (const float*)d_in[1];
    const float* conv_w     = (const float*)d_in[2];
    const float* conv_b     = (const float*)d_in[3];
    const float* norm_w     = (const float*)d_in[4];
    const float* out_proj_w = (const float*)d_in[5];
    const float* dt_bias    = (const float*)d_in[6];
    const float* A_log      = (const float*)d_in[7];
    const float* Dparam     = (const float*)d_in[8];
    float* out = (float*)d_out;

    float *zxbcdt, *convbuf, *ybuf, *xtf, *w1tf, *w2tf, *dtb;
    float *sincb, *state0b, *etb, *cdecb;
    cudaGetSymbolAddress((void**)&zxbcdt,  g_zxbcdt);
    cudaGetSymbolAddress((void**)&convbuf, g_conv);
    cudaGetSymbolAddress((void**)&ybuf,    g_y);
    cudaGetSymbolAddress((void**)&xtf,     g_xtf);
    cudaGetSymbolAddress((void**)&w1tf,    g_w1tf);
    cudaGetSymbolAddress((void**)&w2tf,    g_w2tf);
    cudaGetSymbolAddress((void**)&dtb,     g_dt);
    cudaGetSymbolAddress((void**)&sincb,   g_sinc);
    cudaGetSymbolAddress((void**)&state0b, g_state0);
    cudaGetSymbolAddress((void**)&etb,     g_et);
    cudaGetSymbolAddress((void**)&cdecb,   g_cdec);

    cudaFuncSetAttribute(tf32_gemm_kernel,
                         cudaFuncAttributeMaxDynamicSharedMemorySize, GEMM_SMEM);
    cudaFuncSetAttribute(chunk_kernel,
                         cudaFuncAttributeMaxDynamicSharedMemorySize, CH_SMEM);
    cudaFuncSetAttribute(apply_kernel,
                         cudaFuncAttributeMaxDynamicSharedMemorySize, AP_SMEM);

    // 0) tf32 rounding pre-passes
    {
        long n4;
        n4 = (long)ROWS * DMODEL / 4;
        cvt_tf32_kernel<<<(unsigned)((n4 + 255) / 256), 256>>>(x, xtf, n4);
        n4 = (long)DMODEL * DINPROJ / 4;
        cvt_tf32_kernel<<<(unsigned)((n4 + 255) / 256), 256>>>(in_proj_w, w1tf, n4);
        n4 = (long)DINNER * DMODEL / 4;
        cvt_tf32_kernel<<<(unsigned)((n4 + 255) / 256), 256>>>(out_proj_w, w2tf, n4);
    }

    // 1) in_proj
    {
        dim3 grid((DINPROJ + 127) / 128, ROWS / 128);
        tf32_gemm_kernel<<<grid, 256, GEMM_SMEM>>>(xtf, w1tf, zxbcdt,
                                                   ROWS, DINPROJ, DMODEL);
    }

    // 2) conv + silu
    {
        dim3 grid(CONVDIM / 256, ROWS / 8);
        conv_silu_kernel<<<grid, 256>>>(zxbcdt, conv_w, conv_b, convbuf);
    }

    // 3) dt precompute
    {
        long total = (long)ROWS * NHEADS;
        dt_kernel<<<(unsigned)((total + 255) / 256), 256>>>(zxbcdt, dt_bias, dtb);
    }

    // 4) chunked scan
    chunk_kernel<<<NCTA_CH, 256, CH_SMEM>>>(convbuf, dtb, A_log, Dparam,
                                            ybuf, sincb, etb, cdecb);

    // 5) inter-chunk recurrence
    seq_kernel<<<BATCH * NHEADS, 256>>>(sincb, cdecb, state0b);

    // 6) apply chunk-start states
    apply_kernel<<<NCTA_CH, 256, AP_SMEM>>>(convbuf, state0b, etb, ybuf);

    // 7) gated RMSNorm
    gated_rmsnorm_kernel<<<ROWS, 256>>>(ybuf, zxbcdt, norm_w);

    // 8) out_proj
    {
        dim3 grid(DMODEL / 128, ROWS / 128);
        tf32_gemm_kernel<<<grid, 256, GEMM_SMEM>>>(ybuf, w2tf, out,
                                                   ROWS, DMODEL, DINNER);
    }
}

// round 13
// speedup vs baseline: 1.1791x; 1.0941x over previous
#include <cuda_runtime.h>
#include <cuda_bf16.h>
#include <math.h>
#include <stdint.h>

// ---------------------------------------------------------------------------
// Problem constants (Mamba2 block)
// ---------------------------------------------------------------------------
#define BATCH     2
#define SEQLEN    4096
#define DMODEL    1024
#define DSTATE    128
#define DCONV     4
#define HEADDIM   64
#define DINNER    2048
#define NHEADS    32
#define CONVDIM   2304              // DINNER + 2*DSTATE
#define DINPROJ   4384              // 2*DINNER + 2*DSTATE + NHEADS
#define ROWS      (BATCH*SEQLEN)    // 8192
#define DTCOL     (2*DINNER + 2*DSTATE)   // 4352

#define T_CH      64
#define NCHUNK    (SEQLEN / T_CH)   // 64

// Scratch (allocation-free rule: __device__ globals)
__device__ float g_zxbcdt[(size_t)ROWS * DINPROJ];
__device__ float g_conv  [(size_t)ROWS * CONVDIM];   // tf32-rounded conv+silu
__device__ float g_y     [(size_t)ROWS * DINNER];
__device__ float g_xtf   [(size_t)ROWS * DMODEL];
__device__ float g_w1tf  [(size_t)DMODEL * DINPROJ];
__device__ float g_w2tf  [(size_t)DINNER * DMODEL];

__device__ __forceinline__ uint32_t f2tf32(float f) {
    uint32_t r;
    asm("cvt.rna.tf32.f32 %0, %1;" : "=r"(r) : "f"(f));
    return r;
}
__device__ __forceinline__ float tfr(float f) {
    return __uint_as_float(f2tf32(f));
}
__device__ __forceinline__ uint32_t smem_addr(const void* p) {
    return (uint32_t)__cvta_generic_to_shared(p);
}
__device__ __forceinline__ void cp16(uint32_t dst, const void* src, int sz) {
    asm volatile("cp.async.cg.shared.global [%0], [%1], 16, %2;"
                 :: "r"(dst), "l"(src), "r"(sz) : "memory");
}
__device__ __forceinline__ void cp4(uint32_t dst, const void* src) {
    asm volatile("cp.async.ca.shared.global [%0], [%1], 4;"
                 :: "r"(dst), "l"(src) : "memory");
}
#define CP_COMMIT() asm volatile("cp.async.commit_group;" ::: "memory")
#define CP_WAIT(n)  asm volatile("cp.async.wait_group %0;" :: "n"(n) : "memory")

#define MMA_TF32(acc, a0, a1, a2, a3, b0, b1)                               \
    asm volatile(                                                           \
        "mma.sync.aligned.m16n8k8.row.col.f32.tf32.tf32.f32 "               \
        "{%0,%1,%2,%3}, {%4,%5,%6,%7}, {%8,%9}, {%0,%1,%2,%3};"             \
        : "+f"((acc)[0]), "+f"((acc)[1]), "+f"((acc)[2]), "+f"((acc)[3])    \
        : "r"(a0), "r"(a1), "r"(a2), "r"(a3), "r"(b0), "r"(b1))

// ---------------------------------------------------------------------------
// Elementwise tf32 rounding pre-pass
// ---------------------------------------------------------------------------
__global__ void cvt_tf32_kernel(const float* __restrict__ in,
                                float* __restrict__ out, long n4)
{
    long i = (long)blockIdx.x * blockDim.x + threadIdx.x;
    if (i >= n4) return;
    float4 v = ((const float4*)in)[i];
    float4 o = make_float4(tfr(v.x), tfr(v.y), tfr(v.z), tfr(v.w));
    ((float4*)out)[i] = o;
}

// ---------------------------------------------------------------------------
// TF32 mma.sync GEMM, 3-stage cp.async pipeline (128x128 tile, 2 CTA/SM)
// ---------------------------------------------------------------------------
#define GSTAGES 3
#define ASTR 36
#define BSTR 136
#define STAGE_WORDS (128*ASTR + 32*BSTR)
#define GEMM_SMEM   (GSTAGES * STAGE_WORDS * 4)

__global__ __launch_bounds__(256, 2)
void tf32_gemm_kernel(const float* __restrict__ A, const float* __restrict__ B,
                      float* __restrict__ C, int M, int N, int K)
{
    extern __shared__ uint32_t smem[];

    const int tid   = threadIdx.x;
    const int warp  = tid >> 5;
    const int lane  = tid & 31;
    const int g     = lane >> 2;
    const int t4    = lane & 3;
    const int warpM = warp >> 2;
    const int warpN = warp & 3;
    const int rowC  = blockIdx.y * 128;
    const int colC  = blockIdx.x * 128;
    const int NC    = K / 32;

    auto stage_cp = [&](int chunk, int slot) {
        uint32_t* As = smem + slot * STAGE_WORDS;
        uint32_t* Bs = As + 128 * ASTR;
        const int k0 = chunk * 32;
        #pragma unroll
        for (int p = 0; p < 4; p++) {
            int i = p * 256 + tid;
            int m = i >> 3, kq = i & 7;
            cp16(smem_addr(As + m * ASTR + kq * 4),
                 A + (size_t)(rowC + m) * K + k0 + kq * 4, 16);
        }
        #pragma unroll
        for (int p = 0; p < 4; p++) {
            int i = p * 256 + tid;
            int kl = i >> 5, nq = i & 31;
            int gcol = colC + nq * 4;
            int ok = (gcol < N);
            cp16(smem_addr(Bs + kl * BSTR + nq * 4),
                 B + (size_t)(k0 + kl) * N + (ok ? gcol : 0), ok ? 16 : 0);
        }
    };

    float acc[4][4][4];
    #pragma unroll
    for (int mi = 0; mi < 4; mi++)
        #pragma unroll
        for (int ni = 0; ni < 4; ni++)
            #pragma unroll
            for (int r = 0; r < 4; r++) acc[mi][ni][r] = 0.f;

    stage_cp(0, 0); CP_COMMIT();
    stage_cp(1, 1); CP_COMMIT();

    for (int i = 0; i < NC; i++) {
        if (i < NC - 1) CP_WAIT(1); else CP_WAIT(0);
        __syncthreads();
        if (i + 2 < NC) { stage_cp(i + 2, (i + 2) % GSTAGES); CP_COMMIT(); }

        const uint32_t* As = smem + (i % GSTAGES) * STAGE_WORDS;
        const uint32_t* Bs = As + 128 * ASTR;

        #pragma unroll
        for (int ks = 0; ks < 4; ks++) {
            const int kk = ks * 8;
            uint32_t af[4][4];
            #pragma unroll
            for (int mi = 0; mi < 4; mi++) {
                int m = warpM * 64 + mi * 16;
                af[mi][0] = As[(m + g)     * ASTR + kk + t4];
                af[mi][1] = As[(m + g + 8) * ASTR + kk + t4];
                af[mi][2] = As[(m + g)     * ASTR + kk + t4 + 4];
                af[mi][3] = As[(m + g + 8) * ASTR + kk + t4 + 4];
            }
            uint32_t bf[4][2];
            #pragma unroll
            for (int ni = 0; ni < 4; ni++) {
                int n = warpN * 32 + ni * 8 + g;
                bf[ni][0] = Bs[(kk + t4)     * BSTR + n];
                bf[ni][1] = Bs[(kk + t4 + 4) * BSTR + n];
            }
            #pragma unroll
            for (int mi = 0; mi < 4; mi++)
                #pragma unroll
                for (int ni = 0; ni < 4; ni++)
                    MMA_TF32(acc[mi][ni], af[mi][0], af[mi][1], af[mi][2],
                             af[mi][3], bf[ni][0], bf[ni][1]);
        }
    }

    #pragma unroll
    for (int mi = 0; mi < 4; mi++) {
        int r0 = rowC + warpM * 64 + mi * 16 + g;
        #pragma unroll
        for (int ni = 0; ni < 4; ni++) {
            int cc = colC + warpN * 32 + ni * 8 + t4 * 2;
            if (cc < N) {
                *(float2*)(C + (size_t)r0 * N + cc)       =
                    make_float2(acc[mi][ni][0], acc[mi][ni][1]);
                *(float2*)(C + (size_t)(r0 + 8) * N + cc) =
                    make_float2(acc[mi][ni][2], acc[mi][ni][3]);
            }
        }
    }
}

// ---------------------------------------------------------------------------
// Causal depthwise conv1d (K=4) + SiLU, sliding-window, 8 timesteps/thread.
// ---------------------------------------------------------------------------
__global__ __launch_bounds__(256)
void conv_silu_kernel(const float* __restrict__ zxbcdt,
                      const float* __restrict__ conv_w,
                      const float* __restrict__ conv_b,
                      float* __restrict__ out)
{
    const int  c  = blockIdx.x * 256 + threadIdx.x;
    const long r0 = (long)blockIdx.y * 8;
    const int  l0 = (int)(r0 & (SEQLEN - 1));

    const float w0 = conv_w[0 * CONVDIM + c];
    const float w1 = conv_w[1 * CONVDIM + c];
    const float w2 = conv_w[2 * CONVDIM + c];
    const float w3 = conv_w[3 * CONVDIM + c];
    const float bias = conv_b[c];

    const float* base = zxbcdt + r0 * DINPROJ + DINNER + c;
    float xm3 = 0.f, xm2 = 0.f, xm1 = 0.f;
    if (l0 > 0) {
        xm3 = base[-3 * (long)DINPROJ];
        xm2 = base[-2 * (long)DINPROJ];
        xm1 = base[-1 * (long)DINPROJ];
    }
    float* orow = out + r0 * CONVDIM + c;
    #pragma unroll
    for (int i = 0; i < 8; i++) {
        float x0 = base[(long)i * DINPROJ];
        float acc = bias + w0 * x0 + w1 * xm1 + w2 * xm2 + w3 * xm3;
        float s = acc / (1.f + __expf(-acc));
        orow[(long)i * CONVDIM] = tfr(s);
        xm3 = xm2; xm2 = xm1; xm1 = x0;
    }
}

// ---------------------------------------------------------------------------
// FUSED chunked scan: one persistent CTA per (b,h); state lives in the SI
// MMA accumulator registers across all 64 chunks. No sinc/state0/et/cdec
// gmem buffers; y written exactly once.
//
// Per chunk: spill state->Ss (tfr), C.S0 GEMM, Gram C.B^T, decay-mask via
// outer product (warp-shuffle dt-cumsum), Y = M.X + et*(C.S0) + D*x,
// state = cdec*state + Xw.B (register accumulate).
//
// Smem (222.8 KB, occ 1): 2 stages x [B 64x132 | C 64x132 | X 64x68 | dt 64]
// + Ss[64x132] + Ms[64x68] + weight arrays. Xw aliases current-stage Cs
// (safe: written after last Cs read, consumed before next prefetch of that
// buffer which is issued after the end-of-chunk barrier).
// ---------------------------------------------------------------------------
#define SC_STG   (8448 + 8448 + 4352 + 64)          // 21312 words per stage
#define SC_WORDS (2*SC_STG + 8448 + 4352 + 4*64 + 8)
#define SC_SMEM  (SC_WORDS * 4)                      // 222,752 B

__global__ __launch_bounds__(256, 1)
void fused_scan_kernel(const float* __restrict__ convout,
                       const float* __restrict__ zxbcdt,
                       const float* __restrict__ dt_bias,
                       const float* __restrict__ A_log,
                       const float* __restrict__ Dparam,
                       float* __restrict__ y)
{
    extern __shared__ float sm[];

    const int bh  = blockIdx.x;          // b*32 + h
    const int b   = bh >> 5;
    const int h   = bh & 31;
    const long rb = (long)b * SEQLEN;
    const int tid  = threadIdx.x;
    const int warp = tid >> 5;
    const int lane = tid & 31;
    const int g    = lane >> 2;
    const int t4   = lane & 3;
    const int wM   = warp >> 2;          // 0..1
    const int wN   = warp & 3;           // 0..3

    const float A   = -__expf(A_log[h]);
    const float Dh  = Dparam[h];
    const float dtb = dt_bias[h];

    float* Ss   = sm + 2 * SC_STG;       // state [p][n], stride 132
    float* Ms   = Ss + 8448;             // masked gram [t][s], stride 68
    float* wrow = Ms + 4352;
    float* wcol = wrow + 64;
    float* swS  = wcol + 64;
    float* set  = swS + 64;
    float* scd  = set + 64;              // [0] = chunk decay

    auto stage = [&](int k, int s) {
        float* Bs  = sm + s * SC_STG;
        float* Cs  = Bs + 8448;
        float* Xs  = Cs + 8448;
        float* dtr = Xs + 4352;
        const long r0 = rb + (long)k * T_CH;
        #pragma unroll
        for (int j = 0; j < 8; j++) {
            int idx = j * 256 + tid;
            int t = idx >> 5, q = idx & 31;
            const float* row = convout + (r0 + t) * CONVDIM;
            cp16(smem_addr(Bs + t * 132 + q * 4), row + DINNER + q * 4, 16);
            cp16(smem_addr(Cs + t * 132 + q * 4), row + DINNER + DSTATE + q * 4, 16);
        }
        #pragma unroll
        for (int j = 0; j < 4; j++) {
            int idx = j * 256 + tid;
            int t = idx >> 4, q = idx & 15;
            cp16(smem_addr(Xs + t * 68 + q * 4),
                 convout + (r0 + t) * CONVDIM + h * HEADDIM + q * 4, 16);
        }
        if (tid < 64)
            cp4(smem_addr(dtr + tid), zxbcdt + (r0 + tid) * DINPROJ + DTCOL + h);
    };

    // Persistent state accumulator [p=64][n=128]: wM*32 x wN*32 tiles.
    float stacc[2][4][4];
    #pragma unroll
    for (int mi = 0; mi < 2; mi++)
        #pragma unroll
        for (int ni = 0; ni < 4; ni++)
            #pragma unroll
            for (int r = 0; r < 4; r++) stacc[mi][ni][r] = 0.f;

    stage(0, 0); CP_COMMIT();

    for (int k = 0; k < NCHUNK; k++) {
        const int s = k & 1;
        if (k + 1 < NCHUNK) { stage(k + 1, s ^ 1); CP_COMMIT(); }

        float* Bs  = sm + s * SC_STG;
        float* Cs  = Bs + 8448;
        float* Xs  = Cs + 8448;
        float* dtr = Xs + 4352;
        float* Xw  = Cs;                 // alias: valid after last Cs read
        const long r0 = rb + (long)k * T_CH;

        // ---- spill state -> Ss (tf32-rounded operand)
        #pragma unroll
        for (int mi = 0; mi < 2; mi++) {
            #pragma unroll
            for (int ni = 0; ni < 4; ni++) {
                int pb = wM * 32 + mi * 16;
                int nb = wN * 32 + ni * 8 + 2 * t4;
                Ss[(pb + g)     * 132 + nb]     = tfr(stacc[mi][ni][0]);
                Ss[(pb + g)     * 132 + nb + 1] = tfr(stacc[mi][ni][1]);
                Ss[(pb + g + 8) * 132 + nb]     = tfr(stacc[mi][ni][2]);
                Ss[(pb + g + 8) * 132 + nb + 1] = tfr(stacc[mi][ni][3]);
            }
        }

        if (k + 1 < NCHUNK) CP_WAIT(1); else CP_WAIT(0);
        __syncthreads();                 // B1: stage k + Ss visible

        // ---- dt softplus + warp-shuffle inclusive cumsum + weights (warp 0)
        if (warp == 0) {
            float rv0 = dtr[lane] + dtb;
            float rv1 = dtr[lane + 32] + dtb;
            float d0 = (rv0 > 20.f) ? rv0 : log1pf(__expf(rv0));
            float d1 = (rv1 > 20.f) ? rv1 : log1pf(__expf(rv1));
            float v0 = d0, v1 = d1;
            #pragma unroll
            for (int off = 1; off < 32; off <<= 1) {
                float u0 = __shfl_up_sync(0xffffffffu, v0, off);
                float u1 = __shfl_up_sync(0xffffffffu, v1, off);
                if (lane >= off) { v0 += u0; v1 += u1; }
            }
            float tot0 = __shfl_sync(0xffffffffu, v0, 31);   // S[31]
            v1 += tot0;
            float ST   = __shfl_sync(0xffffffffu, v1, 31);   // S[63]
            float Smid = tot0;
            wrow[lane]      = __expf(A * (v0 - Smid));
            wrow[lane + 32] = __expf(A * (v1 - Smid));
            wcol[lane]      = d0 * __expf(-A * (v0 - Smid));
            wcol[lane + 32] = d1 * __expf(-A * (v1 - Smid));
            swS[lane]       = d0 * __expf(A * (ST - v0));
            swS[lane + 32]  = d1 * __expf(A * (ST - v1));
            set[lane]       = __expf(A * v0);
            set[lane + 32]  = __expf(A * v1);
            if (lane == 0) scd[0] = __expf(A * ST);
        }
        __syncthreads();                 // B2: weights ready
        const float cd = scd[0];

        // ---- acc_state[t][p] = C . S0^T  (K = n = 128)
        float accs[2][2][4];
        #pragma unroll
        for (int mi = 0; mi < 2; mi++)
            #pragma unroll
            for (int ni = 0; ni < 2; ni++)
                #pragma unroll
                for (int r = 0; r < 4; r++) accs[mi][ni][r] = 0.f;

        #pragma unroll
        for (int ks = 0; ks < 16; ks++) {
            const int kk = ks * 8;
            uint32_t af[2][4], bf[2][2];
            #pragma unroll
            for (int mi = 0; mi < 2; mi++) {
                int m = wM * 32 + mi * 16;
                af[mi][0] = __float_as_uint(Cs[(m + g)     * 132 + kk + t4]);
                af[mi][1] = __float_as_uint(Cs[(m + g + 8) * 132 + kk + t4]);
                af[mi][2] = __float_as_uint(Cs[(m + g)     * 132 + kk + t4 + 4]);
                af[mi][3] = __float_as_uint(Cs[(m + g + 8) * 132 + kk + t4 + 4]);
            }
            #pragma unroll
            for (int ni = 0; ni < 2; ni++) {
                int p = wN * 16 + ni * 8 + g;
                bf[ni][0] = __float_as_uint(Ss[p * 132 + kk + t4]);
                bf[ni][1] = __float_as_uint(Ss[p * 132 + kk + t4 + 4]);
            }
            #pragma unroll
            for (int mi = 0; mi < 2; mi++)
                #pragma unroll
                for (int ni = 0; ni < 2; ni++)
                    MMA_TF32(accs[mi][ni], af[mi][0], af[mi][1], af[mi][2],
                             af[mi][3], bf[ni][0], bf[ni][1]);
        }

        // ---- acc_gram[t][s] = C . B^T  (K = n = 128)
        float accg[2][2][4];
        #pragma unroll
        for (int mi = 0; mi < 2; mi++)
            #pragma unroll
            for (int ni = 0; ni < 2; ni++)
                #pragma unroll
                for (int r = 0; r < 4; r++) accg[mi][ni][r] = 0.f;

        #pragma unroll
        for (int ks = 0; ks < 16; ks++) {
            const int kk = ks * 8;
            uint32_t af[2][4], bf[2][2];
            #pragma unroll
            for (int mi = 0; mi < 2; mi++) {
                int m = wM * 32 + mi * 16;
                af[mi][0] = __float_as_uint(Cs[(m + g)     * 132 + kk + t4]);
                af[mi][1] = __float_as_uint(Cs[(m + g + 8) * 132 + kk + t4]);
                af[mi][2] = __float_as_uint(Cs[(m + g)     * 132 + kk + t4 + 4]);
                af[mi][3] = __float_as_uint(Cs[(m + g + 8) * 132 + kk + t4 + 4]);
            }
            #pragma unroll
            for (int ni = 0; ni < 2; ni++) {
                int ss = wN * 16 + ni * 8 + g;
                bf[ni][0] = __float_as_uint(Bs[ss * 132 + kk + t4]);
                bf[ni][1] = __float_as_uint(Bs[ss * 132 + kk + t4 + 4]);
            }
            #pragma unroll
            for (int mi = 0; mi < 2; mi++)
                #pragma unroll
                for (int ni = 0; ni < 2; ni++)
                    MMA_TF32(accg[mi][ni], af[mi][0], af[mi][1], af[mi][2],
                             af[mi][3], bf[ni][0], bf[ni][1]);
        }
        __syncthreads();                 // B3: all Cs/Ss reads done

        // ---- mask -> Ms (outer-product weights); Xw[p][t] = swS_t * x[t][p]
        #pragma unroll
        for (int mi = 0; mi < 2; mi++) {
            #pragma unroll
            for (int ni = 0; ni < 2; ni++) {
                int tb = wM * 32 + mi * 16;
                int sb = wN * 16 + ni * 8 + 2 * t4;
                #pragma unroll
                for (int r = 0; r < 4; r++) {
                    int tt = tb + g + ((r >= 2) ? 8 : 0);
                    int ss = sb + (r & 1);
                    float w = (ss <= tt) ? wrow[tt] * wcol[ss] : 0.f;
                    Ms[tt * 68 + ss] = tfr(accg[mi][ni][r] * w);
                }
            }
        }
        #pragma unroll
        for (int j = 0; j < 16; j++) {
            int idx = j * 256 + tid;
            int p = idx >> 6, t = idx & 63;
            Xw[p * 68 + t] = tfr(swS[t] * Xs[t * 68 + p]);
        }
        __syncthreads();                 // B4: Ms + Xw ready

        // ---- acc_y[t][p] = M . X  (K = s = 64; reuse accg)
        #pragma unroll
        for (int mi = 0; mi < 2; mi++)
            #pragma unroll
            for (int ni = 0; ni < 2; ni++)
                #pragma unroll
                for (int r = 0; r < 4; r++) accg[mi][ni][r] = 0.f;

        #pragma unroll
        for (int ks = 0; ks < 8; ks++) {
            const int kk = ks * 8;
            uint32_t af[2][4], bf[2][2];
            #pragma unroll
            for (int mi = 0; mi < 2; mi++) {
                int m = wM * 32 + mi * 16;
                af[mi][0] = __float_as_uint(Ms[(m + g)     * 68 + kk + t4]);
                af[mi][1] = __float_as_uint(Ms[(m + g + 8) * 68 + kk + t4]);
                af[mi][2] = __float_as_uint(Ms[(m + g)     * 68 + kk + t4 + 4]);
                af[mi][3] = __float_as_uint(Ms[(m + g + 8) * 68 + kk + t4 + 4]);
            }
            #pragma unroll
            for (int ni = 0; ni < 2; ni++) {
                int p = wN * 16 + ni * 8 + g;
                bf[ni][0] = __float_as_uint(Xs[(kk + t4)     * 68 + p]);
                bf[ni][1] = __float_as_uint(Xs[(kk + t4 + 4) * 68 + p]);
            }
            #pragma unroll
            for (int mi = 0; mi < 2; mi++)
                #pragma unroll
                for (int ni = 0; ni < 2; ni++)
                    MMA_TF32(accg[mi][ni], af[mi][0], af[mi][1], af[mi][2],
                             af[mi][3], bf[ni][0], bf[ni][1]);
        }

        // ---- epilogue: y = Y_intra + et*(C.S0) + D*x  (single write)
        #pragma unroll
        for (int mi = 0; mi < 2; mi++) {
            #pragma unroll
            for (int ni = 0; ni < 2; ni++) {
                int tb = wM * 32 + mi * 16;
                int pb = wN * 16 + ni * 8 + 2 * t4;
                int t0 = tb + g, t1 = tb + g + 8;
                float e0 = set[t0], e1 = set[t1];
                float2 o0 = make_float2(
                    accg[mi][ni][0] + e0 * accs[mi][ni][0] + Dh * Xs[t0 * 68 + pb],
                    accg[mi][ni][1] + e0 * accs[mi][ni][1] + Dh * Xs[t0 * 68 + pb + 1]);
                float2 o1 = make_float2(
                    accg[mi][ni][2] + e1 * accs[mi][ni][2] + Dh * Xs[t1 * 68 + pb],
                    accg[mi][ni][3] + e1 * accs[mi][ni][3] + Dh * Xs[t1 * 68 + pb + 1]);
                *(float2*)(y + (r0 + t0) * DINNER + h * HEADDIM + pb) = o0;
                *(float2*)(y + (r0 + t1) * DINNER + h * HEADDIM + pb) = o1;
            }
        }

        // ---- state update: stacc = cd*stacc + Xw . B  (K = t = 64)
        #pragma unroll
        for (int mi = 0; mi < 2; mi++)
            #pragma unroll
            for (int ni = 0; ni < 4; ni++)
                #pragma unroll
                for (int r = 0; r < 4; r++) stacc[mi][ni][r] *= cd;

        #pragma unroll
        for (int ks = 0; ks < 8; ks++) {
            const int kk = ks * 8;
            uint32_t af[2][4], bf[4][2];
            #pragma unroll
            for (int mi = 0; mi < 2; mi++) {
                int p = wM * 32 + mi * 16;
                af[mi][0] = __float_as_uint(Xw[(p + g)     * 68 + kk + t4]);
                af[mi][1] = __float_as_uint(Xw[(p + g + 8) * 68 + kk + t4]);
                af[mi][2] = __float_as_uint(Xw[(p + g)     * 68 + kk + t4 + 4]);
                af[mi][3] = __float_as_uint(Xw[(p + g + 8) * 68 + kk + t4 + 4]);
            }
            #pragma unroll
            for (int ni = 0; ni < 4; ni++) {
                int n = wN * 32 + ni * 8 + g;
                bf[ni][0] = __float_as_uint(Bs[(kk + t4)     * 132 + n]);
                bf[ni][1] = __float_as_uint(Bs[(kk + t4 + 4) * 132 + n]);
            }
            #pragma unroll
            for (int mi = 0; mi < 2; mi++)
                #pragma unroll
                for (int ni = 0; ni < 4; ni++)
                    MMA_TF32(stacc[mi][ni], af[mi][0], af[mi][1], af[mi][2],
                             af[mi][3], bf[ni][0], bf[ni][1]);
        }
        __syncthreads();   // B5: Bs/Xs/Ms/Xw reads done before buf s is re-staged
    }
}

// ---------------------------------------------------------------------------
// Gated RMSNorm in place on y; output tf32-rounded.
// ---------------------------------------------------------------------------
__global__ __launch_bounds__(256)
void gated_rmsnorm_kernel(float* __restrict__ y,
                          const float* __restrict__ zxbcdt,
                          const float* __restrict__ norm_w)
{
    long r = blockIdx.x;
    int tid = threadIdx.x;
    float* yr = y + r * DINNER;
    const float* zr = zxbcdt + r * DINPROJ;

    float vals[8];
    float ss = 0.f;
    #pragma unroll
    for (int i = 0; i < 8; i++) {
        int c = tid + i * 256;
        float z  = zr[c];
        float gv = yr[c] * (z / (1.f + __expf(-z)));
        vals[i] = gv;
        ss = fmaf(gv, gv, ss);
    }

    __shared__ float sred[256];
    sred[tid] = ss;
    __syncthreads();
    #pragma unroll
    for (int off = 128; off > 0; off >>= 1) {
        if (tid < off) sred[tid] += sred[tid + off];
        __syncthreads();
    }
    float scale = rsqrtf(sred[0] / (float)DINNER + 1e-5f);

    #pragma unroll
    for (int i = 0; i < 8; i++) {
        int c = tid + i * 256;
        yr[c] = tfr(vals[i] * scale * norm_w[c]);
    }
}

// ---------------------------------------------------------------------------
// Launch. Inputs: x, in_proj_w, conv_w, conv_b, norm_w, out_proj_w,
//                 dt_bias, A_log, D
// ---------------------------------------------------------------------------
extern "C" void kernel_launch(void* const* d_in, const int* in_sizes, int n_in,
                              void* d_out, int out_size)
{
    const float* x          = (const float*)d_in[0];
    const float* in_proj_w  = (const float*)d_in[1];
    const float* conv_w     = (const float*)d_in[2];
    const float* conv_b     = (const float*)d_in[3];
    const float* norm_w     = (const float*)d_in[4];
    const float* out_proj_w = (const float*)d_in[5];
    const float* dt_bias    = (const float*)d_in[6];
    const float* A_log      = (const float*)d_in[7];
    const float* Dparam     = (const float*)d_in[8];
    float* out = (float*)d_out;

    float *zxbcdt, *convbuf, *ybuf, *xtf, *w1tf, *w2tf;
    cudaGetSymbolAddress((void**)&zxbcdt,  g_zxbcdt);
    cudaGetSymbolAddress((void**)&convbuf, g_conv);
    cudaGetSymbolAddress((void**)&ybuf,    g_y);
    cudaGetSymbolAddress((void**)&xtf,     g_xtf);
    cudaGetSymbolAddress((void**)&w1tf,    g_w1tf);
    cudaGetSymbolAddress((void**)&w2tf,    g_w2tf);

    cudaFuncSetAttribute(tf32_gemm_kernel,
                         cudaFuncAttributeMaxDynamicSharedMemorySize, GEMM_SMEM);
    cudaFuncSetAttribute(fused_scan_kernel,
                         cudaFuncAttributeMaxDynamicSharedMemorySize, SC_SMEM);

    // 0) tf32 rounding pre-passes
    {
        long n4;
        n4 = (long)ROWS * DMODEL / 4;
        cvt_tf32_kernel<<<(unsigned)((n4 + 255) / 256), 256>>>(x, xtf, n4);
        n4 = (long)DMODEL * DINPROJ / 4;
        cvt_tf32_kernel<<<(unsigned)((n4 + 255) / 256), 256>>>(in_proj_w, w1tf, n4);
        n4 = (long)DINNER * DMODEL / 4;
        cvt_tf32_kernel<<<(unsigned)((n4 + 255) / 256), 256>>>(out_proj_w, w2tf, n4);
    }

    // 1) in_proj
    {
        dim3 grid((DINPROJ + 127) / 128, ROWS / 128);
        tf32_gemm_kernel<<<grid, 256, GEMM_SMEM>>>(xtf, w1tf, zxbcdt,
                                                   ROWS, DINPROJ, DMODEL);
    }

    // 2) conv + silu
    {
        dim3 grid(CONVDIM / 256, ROWS / 8);
        conv_silu_kernel<<<grid, 256>>>(zxbcdt, conv_w, conv_b, convbuf);
    }

    // 3) fused chunked scan (dt + intra + inter + apply, state in registers)
    fused_scan_kernel<<<BATCH * NHEADS, 256, SC_SMEM>>>(
        convbuf, zxbcdt, dt_bias, A_log, Dparam, ybuf);

    // 4) gated RMSNorm
    gated_rmsnorm_kernel<<<ROWS, 256>>>(ybuf, zxbcdt, norm_w);

    // 5) out_proj
    {
        dim3 grid(DMODEL / 128, ROWS / 128);
        tf32_gemm_kernel<<<grid, 256, GEMM_SMEM>>>(ybuf, w2tf, out,
                                                   ROWS, DMODEL, DINNER);
    }
}

// round 14
// speedup vs baseline: 1.2129x; 1.0287x over previous
#include <cuda_runtime.h>
#include <cuda_bf16.h>
#include <math.h>
#include <stdint.h>

// ---------------------------------------------------------------------------
// Problem constants (Mamba2 block)
// ---------------------------------------------------------------------------
#define BATCH     2
#define SEQLEN    4096
#define DMODEL    1024
#define DSTATE    128
#define DCONV     4
#define HEADDIM   64
#define DINNER    2048
#define NHEADS    32
#define CONVDIM   2304              // DINNER + 2*DSTATE
#define DINPROJ   4384              // 2*DINNER + 2*DSTATE + NHEADS
#define ROWS      (BATCH*SEQLEN)    // 8192
#define DTCOL     (2*DINNER + 2*DSTATE)   // 4352

#define T_CH      64
#define NCHUNK    (SEQLEN / T_CH)   // 64

// Scratch (allocation-free rule: __device__ globals)
__device__ float g_zxbcdt[(size_t)ROWS * DINPROJ];
__device__ float g_conv  [(size_t)ROWS * CONVDIM];   // tf32-rounded conv+silu
__device__ float g_y     [(size_t)ROWS * DINNER];
__device__ float g_xtf   [(size_t)ROWS * DMODEL];
__device__ float g_w1tf  [(size_t)DMODEL * DINPROJ];
__device__ float g_w2tf  [(size_t)DINNER * DMODEL];

__device__ __forceinline__ uint32_t f2tf32(float f) {
    uint32_t r;
    asm("cvt.rna.tf32.f32 %0, %1;" : "=r"(r) : "f"(f));
    return r;
}
__device__ __forceinline__ float tfr(float f) {
    return __uint_as_float(f2tf32(f));
}
__device__ __forceinline__ uint32_t smem_addr(const void* p) {
    return (uint32_t)__cvta_generic_to_shared(p);
}
__device__ __forceinline__ void cp16(uint32_t dst, const void* src, int sz) {
    asm volatile("cp.async.cg.shared.global [%0], [%1], 16, %2;"
                 :: "r"(dst), "l"(src), "r"(sz) : "memory");
}
__device__ __forceinline__ void cp4(uint32_t dst, const void* src) {
    asm volatile("cp.async.ca.shared.global [%0], [%1], 4;"
                 :: "r"(dst), "l"(src) : "memory");
}
#define CP_COMMIT() asm volatile("cp.async.commit_group;" ::: "memory")
#define CP_WAIT(n)  asm volatile("cp.async.wait_group %0;" :: "n"(n) : "memory")

#define MMA_TF32(acc, a0, a1, a2, a3, b0, b1)                               \
    asm volatile(                                                           \
        "mma.sync.aligned.m16n8k8.row.col.f32.tf32.tf32.f32 "               \
        "{%0,%1,%2,%3}, {%4,%5,%6,%7}, {%8,%9}, {%0,%1,%2,%3};"             \
        : "+f"((acc)[0]), "+f"((acc)[1]), "+f"((acc)[2]), "+f"((acc)[3])    \
        : "r"(a0), "r"(a1), "r"(a2), "r"(a3), "r"(b0), "r"(b1))

// ---------------------------------------------------------------------------
// Elementwise tf32 rounding pre-pass
// ---------------------------------------------------------------------------
__global__ void cvt_tf32_kernel(const float* __restrict__ in,
                                float* __restrict__ out, long n4)
{
    long i = (long)blockIdx.x * blockDim.x + threadIdx.x;
    if (i >= n4) return;
    float4 v = ((const float4*)in)[i];
    float4 o = make_float4(tfr(v.x), tfr(v.y), tfr(v.z), tfr(v.w));
    ((float4*)out)[i] = o;
}

// ---------------------------------------------------------------------------
// TF32 mma.sync GEMM, 3-stage cp.async pipeline (128x128 tile, 2 CTA/SM).
// C[r*ldC + c] = sum_k A[r*K + k] * B[k*ldB + c], c < Nb (guarded).
// ---------------------------------------------------------------------------
#define GSTAGES 3
#define ASTR 36
#define BSTR 136
#define STAGE_WORDS (128*ASTR + 32*BSTR)
#define GEMM_SMEM   (GSTAGES * STAGE_WORDS * 4)

__global__ __launch_bounds__(256, 2)
void tf32_gemm_kernel(const float* __restrict__ A, const float* __restrict__ B,
                      float* __restrict__ C, int M, int Nb, int K,
                      int ldB, int ldC)
{
    extern __shared__ uint32_t smem[];

    const int tid   = threadIdx.x;
    const int warp  = tid >> 5;
    const int lane  = tid & 31;
    const int g     = lane >> 2;
    const int t4    = lane & 3;
    const int warpM = warp >> 2;
    const int warpN = warp & 3;
    const int rowC  = blockIdx.y * 128;
    const int colC  = blockIdx.x * 128;
    const int NC    = K / 32;

    auto stage_cp = [&](int chunk, int slot) {
        uint32_t* As = smem + slot * STAGE_WORDS;
        uint32_t* Bs = As + 128 * ASTR;
        const int k0 = chunk * 32;
        #pragma unroll
        for (int p = 0; p < 4; p++) {
            int i = p * 256 + tid;
            int m = i >> 3, kq = i & 7;
            cp16(smem_addr(As + m * ASTR + kq * 4),
                 A + (size_t)(rowC + m) * K + k0 + kq * 4, 16);
        }
        #pragma unroll
        for (int p = 0; p < 4; p++) {
            int i = p * 256 + tid;
            int kl = i >> 5, nq = i & 31;
            int gcol = colC + nq * 4;
            int ok = (gcol < Nb);
            cp16(smem_addr(Bs + kl * BSTR + nq * 4),
                 B + (size_t)(k0 + kl) * ldB + (ok ? gcol : 0), ok ? 16 : 0);
        }
    };

    float acc[4][4][4];
    #pragma unroll
    for (int mi = 0; mi < 4; mi++)
        #pragma unroll
        for (int ni = 0; ni < 4; ni++)
            #pragma unroll
            for (int r = 0; r < 4; r++) acc[mi][ni][r] = 0.f;

    stage_cp(0, 0); CP_COMMIT();
    stage_cp(1, 1); CP_COMMIT();

    for (int i = 0; i < NC; i++) {
        if (i < NC - 1) CP_WAIT(1); else CP_WAIT(0);
        __syncthreads();
        if (i + 2 < NC) { stage_cp(i + 2, (i + 2) % GSTAGES); CP_COMMIT(); }

        const uint32_t* As = smem + (i % GSTAGES) * STAGE_WORDS;
        const uint32_t* Bs = As + 128 * ASTR;

        #pragma unroll
        for (int ks = 0; ks < 4; ks++) {
            const int kk = ks * 8;
            uint32_t af[4][4];
            #pragma unroll
            for (int mi = 0; mi < 4; mi++) {
                int m = warpM * 64 + mi * 16;
                af[mi][0] = As[(m + g)     * ASTR + kk + t4];
                af[mi][1] = As[(m + g + 8) * ASTR + kk + t4];
                af[mi][2] = As[(m + g)     * ASTR + kk + t4 + 4];
                af[mi][3] = As[(m + g + 8) * ASTR + kk + t4 + 4];
            }
            uint32_t bf[4][2];
            #pragma unroll
            for (int ni = 0; ni < 4; ni++) {
                int n = warpN * 32 + ni * 8 + g;
                bf[ni][0] = Bs[(kk + t4)     * BSTR + n];
                bf[ni][1] = Bs[(kk + t4 + 4) * BSTR + n];
            }
            #pragma unroll
            for (int mi = 0; mi < 4; mi++)
                #pragma unroll
                for (int ni = 0; ni < 4; ni++)
                    MMA_TF32(acc[mi][ni], af[mi][0], af[mi][1], af[mi][2],
                             af[mi][3], bf[ni][0], bf[ni][1]);
        }
    }

    #pragma unroll
    for (int mi = 0; mi < 4; mi++) {
        int r0 = rowC + warpM * 64 + mi * 16 + g;
        #pragma unroll
        for (int ni = 0; ni < 4; ni++) {
            int cc = colC + warpN * 32 + ni * 8 + t4 * 2;
            if (cc < Nb) {
                *(float2*)(C + (size_t)r0 * ldC + cc)       =
                    make_float2(acc[mi][ni][0], acc[mi][ni][1]);
                *(float2*)(C + (size_t)(r0 + 8) * ldC + cc) =
                    make_float2(acc[mi][ni][2], acc[mi][ni][3]);
            }
        }
    }
}

// ---------------------------------------------------------------------------
// Causal depthwise conv1d (K=4) + SiLU, sliding-window, 8 timesteps/thread.
// ---------------------------------------------------------------------------
__global__ __launch_bounds__(256)
void conv_silu_kernel(const float* __restrict__ zxbcdt,
                      const float* __restrict__ conv_w,
                      const float* __restrict__ conv_b,
                      float* __restrict__ out)
{
    const int  c  = blockIdx.x * 256 + threadIdx.x;
    const long r0 = (long)blockIdx.y * 8;
    const int  l0 = (int)(r0 & (SEQLEN - 1));

    const float w0 = conv_w[0 * CONVDIM + c];
    const float w1 = conv_w[1 * CONVDIM + c];
    const float w2 = conv_w[2 * CONVDIM + c];
    const float w3 = conv_w[3 * CONVDIM + c];
    const float bias = conv_b[c];

    const float* base = zxbcdt + r0 * DINPROJ + DINNER + c;
    float xm3 = 0.f, xm2 = 0.f, xm1 = 0.f;
    if (l0 > 0) {
        xm3 = base[-3 * (long)DINPROJ];
        xm2 = base[-2 * (long)DINPROJ];
        xm1 = base[-1 * (long)DINPROJ];
    }
    float* orow = out + r0 * CONVDIM + c;
    #pragma unroll
    for (int i = 0; i < 8; i++) {
        float x0 = base[(long)i * DINPROJ];
        float acc = bias + w0 * x0 + w1 * xm1 + w2 * xm2 + w3 * xm3;
        float s = acc / (1.f + __expf(-acc));
        orow[(long)i * CONVDIM] = tfr(s);
        xm3 = xm2; xm2 = xm1; xm1 = x0;
    }
}

// ---------------------------------------------------------------------------
// FUSED chunked scan (one persistent CTA per (b,h); state in registers).
// C.S0 and Gram GEMMs merged into one k-loop sharing the C fragments.
// ---------------------------------------------------------------------------
#define SC_STG   (8448 + 8448 + 4352 + 64)          // 21312 words per stage
#define SC_WORDS (2*SC_STG + 8448 + 4352 + 4*64 + 8)
#define SC_SMEM  (SC_WORDS * 4)                      // 222,752 B

__global__ __launch_bounds__(256, 1)
void fused_scan_kernel(const float* __restrict__ convout,
                       const float* __restrict__ zxbcdt,
                       const float* __restrict__ dt_bias,
                       const float* __restrict__ A_log,
                       const float* __restrict__ Dparam,
                       float* __restrict__ y)
{
    extern __shared__ float sm[];

    const int bh  = blockIdx.x;
    const int b   = bh >> 5;
    const int h   = bh & 31;
    const long rb = (long)b * SEQLEN;
    const int tid  = threadIdx.x;
    const int warp = tid >> 5;
    const int lane = tid & 31;
    const int g    = lane >> 2;
    const int t4   = lane & 3;
    const int wM   = warp >> 2;
    const int wN   = warp & 3;

    const float A   = -__expf(A_log[h]);
    const float Dh  = Dparam[h];
    const float dtb = dt_bias[h];

    float* Ss   = sm + 2 * SC_STG;       // state [p][n], stride 132
    float* Ms   = Ss + 8448;             // masked gram [t][s], stride 68
    float* wrow = Ms + 4352;
    float* wcol = wrow + 64;
    float* swS  = wcol + 64;
    float* set  = swS + 64;
    float* scd  = set + 64;

    auto stage = [&](int k, int s) {
        float* Bs  = sm + s * SC_STG;
        float* Cs  = Bs + 8448;
        float* Xs  = Cs + 8448;
        float* dtr = Xs + 4352;
        const long r0 = rb + (long)k * T_CH;
        #pragma unroll
        for (int j = 0; j < 8; j++) {
            int idx = j * 256 + tid;
            int t = idx >> 5, q = idx & 31;
            const float* row = convout + (r0 + t) * CONVDIM;
            cp16(smem_addr(Bs + t * 132 + q * 4), row + DINNER + q * 4, 16);
            cp16(smem_addr(Cs + t * 132 + q * 4), row + DINNER + DSTATE + q * 4, 16);
        }
        #pragma unroll
        for (int j = 0; j < 4; j++) {
            int idx = j * 256 + tid;
            int t = idx >> 4, q = idx & 15;
            cp16(smem_addr(Xs + t * 68 + q * 4),
                 convout + (r0 + t) * CONVDIM + h * HEADDIM + q * 4, 16);
        }
        if (tid < 64)
            cp4(smem_addr(dtr + tid), zxbcdt + (r0 + tid) * DINPROJ + DTCOL + h);
    };

    float stacc[2][4][4];
    #pragma unroll
    for (int mi = 0; mi < 2; mi++)
        #pragma unroll
        for (int ni = 0; ni < 4; ni++)
            #pragma unroll
            for (int r = 0; r < 4; r++) stacc[mi][ni][r] = 0.f;

    stage(0, 0); CP_COMMIT();

    for (int k = 0; k < NCHUNK; k++) {
        const int s = k & 1;
        if (k + 1 < NCHUNK) { stage(k + 1, s ^ 1); CP_COMMIT(); }

        float* Bs  = sm + s * SC_STG;
        float* Cs  = Bs + 8448;
        float* Xs  = Cs + 8448;
        float* dtr = Xs + 4352;
        float* Xw  = Cs;                 // alias: valid after last Cs read
        const long r0 = rb + (long)k * T_CH;

        // ---- spill state -> Ss (tf32-rounded operand)
        #pragma unroll
        for (int mi = 0; mi < 2; mi++) {
            #pragma unroll
            for (int ni = 0; ni < 4; ni++) {
                int pb = wM * 32 + mi * 16;
                int nb = wN * 32 + ni * 8 + 2 * t4;
                Ss[(pb + g)     * 132 + nb]     = tfr(stacc[mi][ni][0]);
                Ss[(pb + g)     * 132 + nb + 1] = tfr(stacc[mi][ni][1]);
                Ss[(pb + g + 8) * 132 + nb]     = tfr(stacc[mi][ni][2]);
                Ss[(pb + g + 8) * 132 + nb + 1] = tfr(stacc[mi][ni][3]);
            }
        }

        if (k + 1 < NCHUNK) CP_WAIT(1); else CP_WAIT(0);
        __syncthreads();                 // stage k + Ss visible

        // ---- dt softplus + warp-shuffle cumsum + weights (warp 0)
        if (warp == 0) {
            float rv0 = dtr[lane] + dtb;
            float rv1 = dtr[lane + 32] + dtb;
            float d0 = (rv0 > 20.f) ? rv0 : log1pf(__expf(rv0));
            float d1 = (rv1 > 20.f) ? rv1 : log1pf(__expf(rv1));
            float v0 = d0, v1 = d1;
            #pragma unroll
            for (int off = 1; off < 32; off <<= 1) {
                float u0 = __shfl_up_sync(0xffffffffu, v0, off);
                float u1 = __shfl_up_sync(0xffffffffu, v1, off);
                if (lane >= off) { v0 += u0; v1 += u1; }
            }
            float tot0 = __shfl_sync(0xffffffffu, v0, 31);
            v1 += tot0;
            float ST   = __shfl_sync(0xffffffffu, v1, 31);
            float Smid = tot0;
            wrow[lane]      = __expf(A * (v0 - Smid));
            wrow[lane + 32] = __expf(A * (v1 - Smid));
            wcol[lane]      = d0 * __expf(-A * (v0 - Smid));
            wcol[lane + 32] = d1 * __expf(-A * (v1 - Smid));
            swS[lane]       = d0 * __expf(A * (ST - v0));
            swS[lane + 32]  = d1 * __expf(A * (ST - v1));
            set[lane]       = __expf(A * v0);
            set[lane + 32]  = __expf(A * v1);
            if (lane == 0) scd[0] = __expf(A * ST);
        }
        __syncthreads();
        const float cd = scd[0];

        // ---- merged: accs = C.S0^T and accg = C.B^T (shared af, K = 128)
        float accs[2][2][4], accg[2][2][4];
        #pragma unroll
        for (int mi = 0; mi < 2; mi++)
            #pragma unroll
            for (int ni = 0; ni < 2; ni++)
                #pragma unroll
                for (int r = 0; r < 4; r++) { accs[mi][ni][r] = 0.f; accg[mi][ni][r] = 0.f; }

        #pragma unroll
        for (int ks = 0; ks < 16; ks++) {
            const int kk = ks * 8;
            uint32_t af[2][4], bfS[2][2], bfB[2][2];
            #pragma unroll
            for (int mi = 0; mi < 2; mi++) {
                int m = wM * 32 + mi * 16;
                af[mi][0] = __float_as_uint(Cs[(m + g)     * 132 + kk + t4]);
                af[mi][1] = __float_as_uint(Cs[(m + g + 8) * 132 + kk + t4]);
                af[mi][2] = __float_as_uint(Cs[(m + g)     * 132 + kk + t4 + 4]);
                af[mi][3] = __float_as_uint(Cs[(m + g + 8) * 132 + kk + t4 + 4]);
            }
            #pragma unroll
            for (int ni = 0; ni < 2; ni++) {
                int p = wN * 16 + ni * 8 + g;
                bfS[ni][0] = __float_as_uint(Ss[p * 132 + kk + t4]);
                bfS[ni][1] = __float_as_uint(Ss[p * 132 + kk + t4 + 4]);
                bfB[ni][0] = __float_as_uint(Bs[p * 132 + kk + t4]);
                bfB[ni][1] = __float_as_uint(Bs[p * 132 + kk + t4 + 4]);
            }
            #pragma unroll
            for (int mi = 0; mi < 2; mi++)
                #pragma unroll
                for (int ni = 0; ni < 2; ni++) {
                    MMA_TF32(accs[mi][ni], af[mi][0], af[mi][1], af[mi][2],
                             af[mi][3], bfS[ni][0], bfS[ni][1]);
                    MMA_TF32(accg[mi][ni], af[mi][0], af[mi][1], af[mi][2],
                             af[mi][3], bfB[ni][0], bfB[ni][1]);
                }
        }
        __syncthreads();                 // all Cs/Ss reads done

        // ---- mask -> Ms; Xw[p][t] = swS_t * x[t][p]
        #pragma unroll
        for (int mi = 0; mi < 2; mi++) {
            #pragma unroll
            for (int ni = 0; ni < 2; ni++) {
                int tb = wM * 32 + mi * 16;
                int sb = wN * 16 + ni * 8 + 2 * t4;
                #pragma unroll
                for (int r = 0; r < 4; r++) {
                    int tt = tb + g + ((r >= 2) ? 8 : 0);
                    int ss = sb + (r & 1);
                    float w = (ss <= tt) ? wrow[tt] * wcol[ss] : 0.f;
                    Ms[tt * 68 + ss] = tfr(accg[mi][ni][r] * w);
                }
            }
        }
        #pragma unroll
        for (int j = 0; j < 16; j++) {
            int idx = j * 256 + tid;
            int p = idx >> 6, t = idx & 63;
            Xw[p * 68 + t] = tfr(swS[t] * Xs[t * 68 + p]);
        }
        __syncthreads();                 // Ms + Xw ready

        // ---- acc_y[t][p] = M . X (K = 64; reuse accg)
        #pragma unroll
        for (int mi = 0; mi < 2; mi++)
            #pragma unroll
            for (int ni = 0; ni < 2; ni++)
                #pragma unroll
                for (int r = 0; r < 4; r++) accg[mi][ni][r] = 0.f;

        #pragma unroll
        for (int ks = 0; ks < 8; ks++) {
            const int kk = ks * 8;
            uint32_t af[2][4], bf[2][2];
            #pragma unroll
            for (int mi = 0; mi < 2; mi++) {
                int m = wM * 32 + mi * 16;
                af[mi][0] = __float_as_uint(Ms[(m + g)     * 68 + kk + t4]);
                af[mi][1] = __float_as_uint(Ms[(m + g + 8) * 68 + kk + t4]);
                af[mi][2] = __float_as_uint(Ms[(m + g)     * 68 + kk + t4 + 4]);
                af[mi][3] = __float_as_uint(Ms[(m + g + 8) * 68 + kk + t4 + 4]);
            }
            #pragma unroll
            for (int ni = 0; ni < 2; ni++) {
                int p = wN * 16 + ni * 8 + g;
                bf[ni][0] = __float_as_uint(Xs[(kk + t4)     * 68 + p]);
                bf[ni][1] = __float_as_uint(Xs[(kk + t4 + 4) * 68 + p]);
            }
            #pragma unroll
            for (int mi = 0; mi < 2; mi++)
                #pragma unroll
                for (int ni = 0; ni < 2; ni++)
                    MMA_TF32(accg[mi][ni], af[mi][0], af[mi][1], af[mi][2],
                             af[mi][3], bf[ni][0], bf[ni][1]);
        }

        // ---- epilogue: y = Y_intra + et*(C.S0) + D*x (single write)
        #pragma unroll
        for (int mi = 0; mi < 2; mi++) {
            #pragma unroll
            for (int ni = 0; ni < 2; ni++) {
                int tb = wM * 32 + mi * 16;
                int pb = wN * 16 + ni * 8 + 2 * t4;
                int t0 = tb + g, t1 = tb + g + 8;
                float e0 = set[t0], e1 = set[t1];
                float2 o0 = make_float2(
                    accg[mi][ni][0] + e0 * accs[mi][ni][0] + Dh * Xs[t0 * 68 + pb],
                    accg[mi][ni][1] + e0 * accs[mi][ni][1] + Dh * Xs[t0 * 68 + pb + 1]);
                float2 o1 = make_float2(
                    accg[mi][ni][2] + e1 * accs[mi][ni][2] + Dh * Xs[t1 * 68 + pb],
                    accg[mi][ni][3] + e1 * accs[mi][ni][3] + Dh * Xs[t1 * 68 + pb + 1]);
                *(float2*)(y + (r0 + t0) * DINNER + h * HEADDIM + pb) = o0;
                *(float2*)(y + (r0 + t1) * DINNER + h * HEADDIM + pb) = o1;
            }
        }

        // ---- state update: stacc = cd*stacc + Xw . B (K = 64)
        #pragma unroll
        for (int mi = 0; mi < 2; mi++)
            #pragma unroll
            for (int ni = 0; ni < 4; ni++)
                #pragma unroll
                for (int r = 0; r < 4; r++) stacc[mi][ni][r] *= cd;

        #pragma unroll
        for (int ks = 0; ks < 8; ks++) {
            const int kk = ks * 8;
            uint32_t af[2][4], bf[4][2];
            #pragma unroll
            for (int mi = 0; mi < 2; mi++) {
                int p = wM * 32 + mi * 16;
                af[mi][0] = __float_as_uint(Xw[(p + g)     * 68 + kk + t4]);
                af[mi][1] = __float_as_uint(Xw[(p + g + 8) * 68 + kk + t4]);
                af[mi][2] = __float_as_uint(Xw[(p + g)     * 68 + kk + t4 + 4]);
                af[mi][3] = __float_as_uint(Xw[(p + g + 8) * 68 + kk + t4 + 4]);
            }
            #pragma unroll
            for (int ni = 0; ni < 4; ni++) {
                int n = wN * 32 + ni * 8 + g;
                bf[ni][0] = __float_as_uint(Bs[(kk + t4)     * 132 + n]);
                bf[ni][1] = __float_as_uint(Bs[(kk + t4 + 4) * 132 + n]);
            }
            #pragma unroll
            for (int mi = 0; mi < 2; mi++)
                #pragma unroll
                for (int ni = 0; ni < 4; ni++)
                    MMA_TF32(stacc[mi][ni], af[mi][0], af[mi][1], af[mi][2],
                             af[mi][3], bf[ni][0], bf[ni][1]);
        }
        __syncthreads();   // buf s reads done before re-stage
    }
}

// ---------------------------------------------------------------------------
// Gated RMSNorm in place on y; output tf32-rounded.
// ---------------------------------------------------------------------------
__global__ __launch_bounds__(256)
void gated_rmsnorm_kernel(float* __restrict__ y,
                          const float* __restrict__ zxbcdt,
                          const float* __restrict__ norm_w)
{
    long r = blockIdx.x;
    int tid = threadIdx.x;
    float* yr = y + r * DINNER;
    const float* zr = zxbcdt + r * DINPROJ;

    float vals[8];
    float ss = 0.f;
    #pragma unroll
    for (int i = 0; i < 8; i++) {
        int c = tid + i * 256;
        float z  = zr[c];
        float gv = yr[c] * (z / (1.f + __expf(-z)));
        vals[i] = gv;
        ss = fmaf(gv, gv, ss);
    }

    __shared__ float sred[256];
    sred[tid] = ss;
    __syncthreads();
    #pragma unroll
    for (int off = 128; off > 0; off >>= 1) {
        if (tid < off) sred[tid] += sred[tid + off];
        __syncthreads();
    }
    float scale = rsqrtf(sred[0] / (float)DINNER + 1e-5f);

    #pragma unroll
    for (int i = 0; i < 8; i++) {
        int c = tid + i * 256;
        yr[c] = tfr(vals[i] * scale * norm_w[c]);
    }
}

// ---------------------------------------------------------------------------
// Launch. Inputs: x, in_proj_w, conv_w, conv_b, norm_w, out_proj_w,
//                 dt_bias, A_log, D
// Stream overlap: z-columns of in_proj run on a side stream concurrently
// with conv + fused scan (which need only xBC/dt columns).
// ---------------------------------------------------------------------------
extern "C" void kernel_launch(void* const* d_in, const int* in_sizes, int n_in,
                              void* d_out, int out_size)
{
    const float* x          = (const float*)d_in[0];
    const float* in_proj_w  = (const float*)d_in[1];
    const float* conv_w     = (const float*)d_in[2];
    const float* conv_b     = (const float*)d_in[3];
    const float* norm_w     = (const float*)d_in[4];
    const float* out_proj_w = (const float*)d_in[5];
    const float* dt_bias    = (const float*)d_in[6];
    const float* A_log      = (const float*)d_in[7];
    const float* Dparam     = (const float*)d_in[8];
    float* out = (float*)d_out;

    float *zxbcdt, *convbuf, *ybuf, *xtf, *w1tf, *w2tf;
    cudaGetSymbolAddress((void**)&zxbcdt,  g_zxbcdt);
    cudaGetSymbolAddress((void**)&convbuf, g_conv);
    cudaGetSymbolAddress((void**)&ybuf,    g_y);
    cudaGetSymbolAddress((void**)&xtf,     g_xtf);
    cudaGetSymbolAddress((void**)&w1tf,    g_w1tf);
    cudaGetSymbolAddress((void**)&w2tf,    g_w2tf);

    cudaFuncSetAttribute(tf32_gemm_kernel,
                         cudaFuncAttributeMaxDynamicSharedMemorySize, GEMM_SMEM);
    cudaFuncSetAttribute(fused_scan_kernel,
                         cudaFuncAttributeMaxDynamicSharedMemorySize, SC_SMEM);

    static cudaStream_t s1 = nullptr;
    static cudaEvent_t evFork = nullptr, evJoin = nullptr;
    if (s1 == nullptr) {
        cudaStreamCreateWithFlags(&s1, cudaStreamNonBlocking);
        cudaEventCreateWithFlags(&evFork, cudaEventDisableTiming);
        cudaEventCreateWithFlags(&evJoin, cudaEventDisableTiming);
    }

    // 0) tf32 rounding: x and w1 (needed by both in_proj halves)
    {
        long n4;
        n4 = (long)ROWS * DMODEL / 4;
        cvt_tf32_kernel<<<(unsigned)((n4 + 255) / 256), 256>>>(x, xtf, n4);
        n4 = (long)DMODEL * DINPROJ / 4;
        cvt_tf32_kernel<<<(unsigned)((n4 + 255) / 256), 256>>>(in_proj_w, w1tf, n4);
    }

    // Fork side stream (it depends on xtf/w1tf just produced)
    cudaEventRecord(evFork, 0);
    cudaStreamWaitEvent(s1, evFork, 0);

    // ---- side stream: w2 cvt + in_proj z-columns [0, 2048)
    {
        long n4 = (long)DINNER * DMODEL / 4;
        cvt_tf32_kernel<<<(unsigned)((n4 + 255) / 256), 256, 0, s1>>>(
            out_proj_w, w2tf, n4);
        dim3 grid(DINNER / 128, ROWS / 128);     // 16 x 64
        tf32_gemm_kernel<<<grid, 256, GEMM_SMEM, s1>>>(
            xtf, w1tf, zxbcdt, ROWS, DINNER, DMODEL, DINPROJ, DINPROJ);
    }
    cudaEventRecord(evJoin, s1);

    // ---- main stream: in_proj xBC+dt columns [2048, 4384)
    {
        const int NB = DINPROJ - DINNER;          // 2336
        dim3 grid((NB + 127) / 128, ROWS / 128);  // 19 x 64
        tf32_gemm_kernel<<<grid, 256, GEMM_SMEM>>>(
            xtf, w1tf + DINNER, zxbcdt + DINNER, ROWS, NB, DMODEL,
            DINPROJ, DINPROJ);
    }

    // conv + silu (reads cols [2048, 4352))
    {
        dim3 grid(CONVDIM / 256, ROWS / 8);
        conv_silu_kernel<<<grid, 256>>>(zxbcdt, conv_w, conv_b, convbuf);
    }

    // fused chunked scan
    fused_scan_kernel<<<BATCH * NHEADS, 256, SC_SMEM>>>(
        convbuf, zxbcdt, dt_bias, A_log, Dparam, ybuf);

    // join: rmsnorm needs z columns from the side stream
    cudaStreamWaitEvent(0, evJoin, 0);

    // gated RMSNorm
    gated_rmsnorm_kernel<<<ROWS, 256>>>(ybuf, zxbcdt, norm_w);

    // out_proj
    {
        dim3 grid(DMODEL / 128, ROWS / 128);
        tf32_gemm_kernel<<<grid, 256, GEMM_SMEM>>>(
            ybuf, w2tf, out, ROWS, DMODEL, DINNER, DMODEL, DMODEL);
    }
}